// round 2
// baseline (speedup 1.0000x reference)
#include <cuda_runtime.h>
#include <math.h>
#include <stdint.h>

#define NNODES 50000
#define NFEAT  512
#define HHC    512        // H * HC
#define NHEAD  8
#define HC     64
#define NCLS   16
#define NEG    0.2f
#define MAXEN  850000     // E + N self loops

// ---------------- scratch (device globals; no allocation) ----------------
__device__ float g_h1  [(size_t)NNODES * HHC];   // layer1 transformed features
__device__ float g_hact[(size_t)NNODES * HHC];   // elu(emb)
__device__ float g_h2  [(size_t)NNODES * NCLS];  // layer2 transformed features
__device__ float g_as1[NNODES * NHEAD];
__device__ float g_ad1[NNODES * NHEAD];
__device__ float g_m1 [NNODES * NHEAD];
__device__ float g_den1[NNODES * NHEAD];
__device__ float g_as2[NNODES];
__device__ float g_ad2[NNODES];
__device__ float g_m2 [NNODES];
__device__ float g_den2[NNODES];
__device__ float g_ex1[(size_t)MAXEN * NHEAD];
__device__ float g_ex2[MAXEN];
__device__ int   g_src[MAXEN];
__device__ int   g_dst[MAXEN];
__device__ int   g_is64;

// ---------------- helpers ----------------
__device__ __forceinline__ void atomicMaxFloat(float* addr, float v) {
    // init value is -inf; mixed signed-max / unsigned-min trick gives float max
    if (v >= 0.f) atomicMax((int*)addr, __float_as_int(v));
    else          atomicMin((unsigned int*)addr, (unsigned int)__float_as_int(v));
}

// ---------------- edge dtype sniff + canonicalization ----------------
// If edge_index is int64, every odd 32-bit word is the zero high-half
// (all values in [0, 50000)). If int32, odd words are random node ids.
__global__ void k_detect(const unsigned int* __restrict__ ei32) {
    __shared__ int nz;
    if (threadIdx.x == 0) nz = 0;
    __syncthreads();
    // inspect 4096 odd words
    for (int i = threadIdx.x; i < 4096; i += blockDim.x)
        if (ei32[2 * i + 1] != 0u) atomicOr(&nz, 1);
    __syncthreads();
    if (threadIdx.x == 0) g_is64 = nz ? 0 : 1;
}

__global__ void k_convert(const void* __restrict__ ei, int E, int EN) {
    int e = blockIdx.x * blockDim.x + threadIdx.x;
    if (e >= EN) return;
    int s, d;
    if (e < E) {
        if (g_is64) {
            const long long* p = (const long long*)ei;
            s = (int)p[e]; d = (int)p[(size_t)E + e];
        } else {
            const int* p = (const int*)ei;
            s = p[e]; d = p[E + e];
        }
    } else { s = e - E; d = e - E; }
    g_src[e] = s; g_dst[e] = d;
}

// ---------------- init ----------------
__global__ void k_zero(float* __restrict__ p, size_t n) {
    size_t i = (size_t)blockIdx.x * blockDim.x + threadIdx.x;
    if (i < n) p[i] = 0.f;
}

__global__ void k_init_aux(int M) {
    int i = blockIdx.x * blockDim.x + threadIdx.x;
    float ninf = __int_as_float(0xff800000);
    if (i < M * NHEAD) { g_m1[i] = ninf; g_den1[i] = 0.f; }
    if (i < M)         { g_m2[i] = ninf; g_den2[i] = 0.f; }
}

// ---------------- GEMM1: h1 = x @ W1   (M x 512) @ (512 x 512) ----------------
__global__ void k_gemm1(const float* __restrict__ A, const float* __restrict__ B, int M) {
    __shared__ float As[16][64];
    __shared__ float Bs[16][64];
    int tid = threadIdx.x;
    int tx = tid & 15, ty = tid >> 4;
    int rowBase = blockIdx.y << 6;
    int colBase = blockIdx.x << 6;
    float acc[4][4];
#pragma unroll
    for (int i = 0; i < 4; i++)
#pragma unroll
        for (int j = 0; j < 4; j++) acc[i][j] = 0.f;

    for (int k0 = 0; k0 < NFEAT; k0 += 16) {
#pragma unroll
        for (int i = 0; i < 4; i++) {
            int idx = tid + (i << 8);
            int m = idx >> 4, kk = idx & 15;
            int r = rowBase + m;
            As[kk][m] = (r < M) ? A[(size_t)r * NFEAT + k0 + kk] : 0.f;
        }
#pragma unroll
        for (int i = 0; i < 4; i++) {
            int idx = tid + (i << 8);
            int kk = idx >> 6, c = idx & 63;
            Bs[kk][c] = B[(size_t)(k0 + kk) * HHC + colBase + c];
        }
        __syncthreads();
#pragma unroll
        for (int kk = 0; kk < 16; kk++) {
            float a[4], b[4];
#pragma unroll
            for (int i = 0; i < 4; i++) a[i] = As[kk][(ty << 2) + i];
#pragma unroll
            for (int j = 0; j < 4; j++) b[j] = Bs[kk][(tx << 2) + j];
#pragma unroll
            for (int i = 0; i < 4; i++)
#pragma unroll
                for (int j = 0; j < 4; j++) acc[i][j] += a[i] * b[j];
        }
        __syncthreads();
    }
#pragma unroll
    for (int i = 0; i < 4; i++) {
        int r = rowBase + (ty << 2) + i;
        if (r < M) {
#pragma unroll
            for (int j = 0; j < 4; j++)
                g_h1[(size_t)r * HHC + colBase + (tx << 2) + j] = acc[i][j];
        }
    }
}

// ---------------- alpha1: per-node per-head dot products (warp per node) -----
__global__ void k_alpha1(const float* __restrict__ asrc, const float* __restrict__ adst, int M) {
    int gw = (blockIdx.x * blockDim.x + threadIdx.x) >> 5;
    int lane = threadIdx.x & 31;
    if (gw >= M) return;
    const float* hr = g_h1 + (size_t)gw * HHC;
#pragma unroll
    for (int h = 0; h < NHEAD; h++) {
        float v0 = hr[h * 64 + lane], v1 = hr[h * 64 + 32 + lane];
        float sa = v0 * asrc[h * 64 + lane] + v1 * asrc[h * 64 + 32 + lane];
        float sd = v0 * adst[h * 64 + lane] + v1 * adst[h * 64 + 32 + lane];
#pragma unroll
        for (int o = 16; o; o >>= 1) {
            sa += __shfl_down_sync(0xffffffffu, sa, o);
            sd += __shfl_down_sync(0xffffffffu, sd, o);
        }
        if (lane == 0) { g_as1[gw * 8 + h] = sa; g_ad1[gw * 8 + h] = sd; }
    }
}

// ---------------- layer1 softmax passes ----------------
__global__ void k_edgemax1(int EN) {
    int idx = blockIdx.x * blockDim.x + threadIdx.x;
    if (idx >= EN * NHEAD) return;
    int e = idx >> 3, h = idx & 7;
    int s = g_src[e], d = g_dst[e];
    float v = g_as1[s * 8 + h] + g_ad1[d * 8 + h];
    v = v >= 0.f ? v : NEG * v;
    atomicMaxFloat(&g_m1[d * 8 + h], v);
}

__global__ void k_edgeexp1(int EN) {
    int idx = blockIdx.x * blockDim.x + threadIdx.x;
    if (idx >= EN * NHEAD) return;
    int e = idx >> 3, h = idx & 7;
    int s = g_src[e], d = g_dst[e];
    float v = g_as1[s * 8 + h] + g_ad1[d * 8 + h];
    v = v >= 0.f ? v : NEG * v;
    float ex = expf(v - g_m1[d * 8 + h]);
    g_ex1[(size_t)e * 8 + h] = ex;
    atomicAdd(&g_den1[d * 8 + h], ex);
}

// ---------------- layer1 aggregation: block per edge ----------------
__global__ void k_aggr1(float* __restrict__ emb) {
    int e = blockIdx.x;
    int s = g_src[e], d = g_dst[e];
    __shared__ float alpha[8];
    if (threadIdx.x < 8)
        alpha[threadIdx.x] = g_ex1[(size_t)e * 8 + threadIdx.x] / g_den1[d * 8 + threadIdx.x];
    __syncthreads();
    int t = threadIdx.x;                       // 128 threads, 4 floats each
    float4 hv = ((const float4*)(g_h1 + (size_t)s * HHC))[t];
    float a = alpha[t >> 4];                   // (t*4)/64
    float* o = emb + (size_t)d * HHC + (t << 2);
    atomicAdd(o + 0, hv.x * a);
    atomicAdd(o + 1, hv.y * a);
    atomicAdd(o + 2, hv.z * a);
    atomicAdd(o + 3, hv.w * a);
}

// ---------------- bias + elu ----------------
__global__ void k_elu(float* __restrict__ emb, const float* __restrict__ b1, int M) {
    size_t i = (size_t)blockIdx.x * blockDim.x + threadIdx.x;
    if (i >= (size_t)M * HHC) return;
    float v = emb[i] + b1[i & 511];
    emb[i] = v;
    g_hact[i] = v > 0.f ? v : expm1f(v);
}

// ---------------- GEMM2: h2 = hact @ W2  (M x 512) @ (512 x 16) ----------------
__global__ void k_gemm2(const float* __restrict__ W2, int M) {
    __shared__ float Ws[NFEAT * NCLS];         // 32 KB
    for (int i = threadIdx.x; i < NFEAT * NCLS; i += 256) Ws[i] = W2[i];
    __syncthreads();
    int c = threadIdx.x & 15;
    int n = blockIdx.x * 16 + (threadIdx.x >> 4);
    if (n >= M) return;
    const float4* hr4 = (const float4*)(g_hact + (size_t)n * HHC);
    float acc = 0.f;
#pragma unroll 8
    for (int k4 = 0; k4 < NFEAT / 4; k4++) {
        float4 hv = hr4[k4];
        int k = k4 * 4;
        acc += hv.x * Ws[(k + 0) * NCLS + c];
        acc += hv.y * Ws[(k + 1) * NCLS + c];
        acc += hv.z * Ws[(k + 2) * NCLS + c];
        acc += hv.w * Ws[(k + 3) * NCLS + c];
    }
    g_h2[(size_t)n * NCLS + c] = acc;
}

// ---------------- alpha2 ----------------
__global__ void k_alpha2(const float* __restrict__ asrc, const float* __restrict__ adst, int M) {
    int n = blockIdx.x * blockDim.x + threadIdx.x;
    if (n >= M) return;
    const float* hr = g_h2 + (size_t)n * NCLS;
    float sa = 0.f, sd = 0.f;
#pragma unroll
    for (int c = 0; c < NCLS; c++) {
        float v = hr[c];
        sa += v * asrc[c];
        sd += v * adst[c];
    }
    g_as2[n] = sa; g_ad2[n] = sd;
}

// ---------------- layer2 softmax passes ----------------
__global__ void k_edgemax2(int EN) {
    int e = blockIdx.x * blockDim.x + threadIdx.x;
    if (e >= EN) return;
    int s = g_src[e], d = g_dst[e];
    float v = g_as2[s] + g_ad2[d];
    v = v >= 0.f ? v : NEG * v;
    atomicMaxFloat(&g_m2[d], v);
}

__global__ void k_edgeexp2(int EN) {
    int e = blockIdx.x * blockDim.x + threadIdx.x;
    if (e >= EN) return;
    int s = g_src[e], d = g_dst[e];
    float v = g_as2[s] + g_ad2[d];
    v = v >= 0.f ? v : NEG * v;
    float ex = expf(v - g_m2[d]);
    g_ex2[e] = ex;
    atomicAdd(&g_den2[d], ex);
}

// ---------------- layer2 aggregation: thread per (edge, class) ----------------
__global__ void k_aggr2(float* __restrict__ logits, int EN) {
    int idx = blockIdx.x * blockDim.x + threadIdx.x;
    if (idx >= EN * NCLS) return;
    int e = idx >> 4, c = idx & 15;
    int s = g_src[e], d = g_dst[e];
    float alpha = g_ex2[e] / g_den2[d];
    atomicAdd(&logits[(size_t)d * NCLS + c], g_h2[(size_t)s * NCLS + c] * alpha);
}

__global__ void k_bias2(float* __restrict__ logits, const float* __restrict__ b2, int M) {
    int i = blockIdx.x * blockDim.x + threadIdx.x;
    if (i < M * NCLS) logits[i] += b2[i & 15];
}

// ---------------- launch ----------------
extern "C" void kernel_launch(void* const* d_in, const int* in_sizes, int n_in,
                              void* d_out, int out_size) {
    const float* x     = (const float*)d_in[0];
    const void*  ei    = d_in[1];
    const float* w1    = (const float*)d_in[2];
    const float* asrc1 = (const float*)d_in[3];
    const float* adst1 = (const float*)d_in[4];
    const float* b1    = (const float*)d_in[5];
    const float* w2    = (const float*)d_in[6];
    const float* asrc2 = (const float*)d_in[7];
    const float* adst2 = (const float*)d_in[8];
    const float* b2    = (const float*)d_in[9];

    const int M  = in_sizes[0] / NFEAT;     // 50000
    const int E  = in_sizes[1] / 2;         // 800000
    const int EN = E + M;                   // 850000

    float* logits = (float*)d_out;                    // [M, 16]
    float* emb    = logits + (size_t)M * NCLS;        // [M, 512]

    const size_t outN = (size_t)out_size;

    // edge dtype sniff + canonicalize to int32 src/dst with self loops
    k_detect<<<1, 256>>>((const unsigned int*)ei);
    k_convert<<<(EN + 255) / 256, 256>>>(ei, E, EN);

    // init
    k_zero<<<(unsigned)((outN + 255) / 256), 256>>>((float*)d_out, outN);
    k_init_aux<<<(M * NHEAD + 255) / 256, 256>>>(M);

    // layer 1
    {
        dim3 grid(HHC / 64, (M + 63) / 64);
        k_gemm1<<<grid, 256>>>(x, w1, M);
    }
    k_alpha1<<<((M * 32) + 255) / 256, 256>>>(asrc1, adst1, M);
    k_edgemax1<<<(EN * NHEAD + 255) / 256, 256>>>(EN);
    k_edgeexp1<<<(EN * NHEAD + 255) / 256, 256>>>(EN);
    k_aggr1<<<EN, 128>>>(emb);
    k_elu<<<(unsigned)(((size_t)M * HHC + 255) / 256), 256>>>(emb, b1, M);

    // layer 2
    k_gemm2<<<(M + 15) / 16, 256>>>(w2, M);
    k_alpha2<<<(M + 255) / 256, 256>>>(asrc2, adst2, M);
    k_edgemax2<<<(EN + 255) / 256, 256>>>(EN);
    k_edgeexp2<<<(EN + 255) / 256, 256>>>(EN);
    k_aggr2<<<(EN * NCLS + 255) / 256, 256>>>(logits, EN);
    k_bias2<<<(M * NCLS + 255) / 256, 256>>>(logits, b2, M);
}

// round 3
// speedup vs baseline: 2.1983x; 2.1983x over previous
#include <cuda_runtime.h>
#include <math.h>
#include <stdint.h>

#define NNODES 50000
#define NFEAT  512
#define HHC    512
#define NHEAD  8
#define NCLS   16
#define NEG    0.2f
#define MAXEN  850000

// ---------------- scratch ----------------
__device__ float g_h1  [(size_t)NNODES * HHC];
__device__ float g_hact[(size_t)NNODES * HHC];
__device__ float g_h2  [(size_t)NNODES * NCLS];
__device__ float g_as1[NNODES * NHEAD];
__device__ float g_ad1[NNODES * NHEAD];
__device__ float g_inv1[NNODES * NHEAD];     // 1/den per (node, head)
__device__ float g_as2[NNODES];
__device__ float g_ad2[NNODES];
__device__ float g_inv2[NNODES];
__device__ float g_ex1[(size_t)MAXEN * NHEAD];
__device__ float g_ex2[MAXEN];
__device__ int   g_src[MAXEN];
__device__ int   g_dst[MAXEN];
__device__ int   g_csrc[MAXEN];              // CSR: src per slot, grouped by dst
__device__ int   g_row[NNODES + 1];
__device__ int   g_deg[NNODES];
__device__ int   g_fill[NNODES];
__device__ int   g_is64;

// ---------------- edge dtype sniff + canonicalization ----------------
__global__ void k_detect(const unsigned int* __restrict__ ei32) {
    __shared__ int nz;
    if (threadIdx.x == 0) nz = 0;
    __syncthreads();
    for (int i = threadIdx.x; i < 4096; i += blockDim.x)
        if (ei32[2 * i + 1] != 0u) atomicOr(&nz, 1);
    __syncthreads();
    if (threadIdx.x == 0) g_is64 = nz ? 0 : 1;
}

__global__ void k_convert(const void* __restrict__ ei, int E, int EN) {
    int e = blockIdx.x * blockDim.x + threadIdx.x;
    if (e >= EN) return;
    int s, d;
    if (e < E) {
        if (g_is64) {
            const long long* p = (const long long*)ei;
            s = (int)p[e]; d = (int)p[(size_t)E + e];
        } else {
            const int* p = (const int*)ei;
            s = p[e]; d = p[E + e];
        }
    } else { s = e - E; d = e - E; }
    g_src[e] = s; g_dst[e] = d;
}

// ---------------- CSR build ----------------
__global__ void k_init0(int M) {
    int i = blockIdx.x * blockDim.x + threadIdx.x;
    if (i < M) { g_deg[i] = 0; g_fill[i] = 0; }
}
__global__ void k_count(int EN) {
    int e = blockIdx.x * blockDim.x + threadIdx.x;
    if (e < EN) atomicAdd(&g_deg[g_dst[e]], 1);
}
__global__ void k_scan(int M) {
    __shared__ int ss[1024];
    int t = threadIdx.x;
    int CH = (M + 1023) >> 10;
    int base = t * CH;
    int sum = 0;
    for (int i = 0; i < CH; i++) { int idx = base + i; if (idx < M) sum += g_deg[idx]; }
    ss[t] = sum; __syncthreads();
    for (int off = 1; off < 1024; off <<= 1) {
        int v = (t >= off) ? ss[t - off] : 0;
        __syncthreads();
        ss[t] += v;
        __syncthreads();
    }
    int off = (t == 0) ? 0 : ss[t - 1];
    for (int i = 0; i < CH; i++) {
        int idx = base + i;
        if (idx < M) { g_row[idx] = off; off += g_deg[idx]; }
    }
    if (t == 1023) g_row[M] = ss[1023];
}
__global__ void k_scatter(int EN) {
    int e = blockIdx.x * blockDim.x + threadIdx.x;
    if (e >= EN) return;
    int d = g_dst[e];
    int p = g_row[d] + atomicAdd(&g_fill[d], 1);
    g_csrc[p] = g_src[e];
}

// ---------------- GEMM1: 128x128x8 tile, 8x8 per thread ----------------
__global__ void __launch_bounds__(256) k_gemm1(const float* __restrict__ A,
                                               const float* __restrict__ B, int M) {
    __shared__ float As[8][132];
    __shared__ float Bs[8][128];
    int tid = threadIdx.x;
    int rowBase = blockIdx.y << 7;
    int colBase = blockIdx.x << 7;
    int tx = tid & 15, ty = tid >> 4;

    float acc[8][8];
#pragma unroll
    for (int i = 0; i < 8; i++)
#pragma unroll
        for (int j = 0; j < 8; j++) acc[i][j] = 0.f;

    int aRow = tid >> 1, aCol = (tid & 1) << 2;   // 128 rows x 8 k, float4
    int bRow = tid >> 5, bCol = (tid & 31) << 2;  // 8 k x 128 cols, float4

    for (int k0 = 0; k0 < NFEAT; k0 += 8) {
        int r = rowBase + aRow;
        float4 av = make_float4(0.f, 0.f, 0.f, 0.f);
        if (r < M) av = *(const float4*)&A[(size_t)r * NFEAT + k0 + aCol];
        As[aCol + 0][aRow] = av.x;
        As[aCol + 1][aRow] = av.y;
        As[aCol + 2][aRow] = av.z;
        As[aCol + 3][aRow] = av.w;
        float4 bv = *(const float4*)&B[(size_t)(k0 + bRow) * HHC + colBase + bCol];
        *(float4*)&Bs[bRow][bCol] = bv;
        __syncthreads();
#pragma unroll
        for (int kk = 0; kk < 8; kk++) {
            float a[8], b[8];
#pragma unroll
            for (int i = 0; i < 8; i++) a[i] = As[kk][(ty << 3) + i];
            float4 b0 = *(float4*)&Bs[kk][(tx << 3)];
            float4 b1 = *(float4*)&Bs[kk][(tx << 3) + 4];
            b[0] = b0.x; b[1] = b0.y; b[2] = b0.z; b[3] = b0.w;
            b[4] = b1.x; b[5] = b1.y; b[6] = b1.z; b[7] = b1.w;
#pragma unroll
            for (int i = 0; i < 8; i++)
#pragma unroll
                for (int j = 0; j < 8; j++) acc[i][j] += a[i] * b[j];
        }
        __syncthreads();
    }
#pragma unroll
    for (int i = 0; i < 8; i++) {
        int r = rowBase + (ty << 3) + i;
        if (r < M) {
            float* o = &g_h1[(size_t)r * HHC + colBase + (tx << 3)];
            *(float4*)o       = make_float4(acc[i][0], acc[i][1], acc[i][2], acc[i][3]);
            *(float4*)(o + 4) = make_float4(acc[i][4], acc[i][5], acc[i][6], acc[i][7]);
        }
    }
}

// ---------------- alpha1 ----------------
__global__ void k_alpha1(const float* __restrict__ asrc, const float* __restrict__ adst, int M) {
    int gw = (blockIdx.x * blockDim.x + threadIdx.x) >> 5;
    int lane = threadIdx.x & 31;
    if (gw >= M) return;
    const float* hr = g_h1 + (size_t)gw * HHC;
#pragma unroll
    for (int h = 0; h < NHEAD; h++) {
        float v0 = hr[h * 64 + lane], v1 = hr[h * 64 + 32 + lane];
        float sa = v0 * asrc[h * 64 + lane] + v1 * asrc[h * 64 + 32 + lane];
        float sd = v0 * adst[h * 64 + lane] + v1 * adst[h * 64 + 32 + lane];
#pragma unroll
        for (int o = 16; o; o >>= 1) {
            sa += __shfl_down_sync(0xffffffffu, sa, o);
            sd += __shfl_down_sync(0xffffffffu, sd, o);
        }
        if (lane == 0) { g_as1[gw * 8 + h] = sa; g_ad1[gw * 8 + h] = sd; }
    }
}

// ---------------- layer1 softmax: warp per dst node, no atomics ----------------
__global__ void k_soft1(int M) {
    int n = (blockIdx.x * blockDim.x + threadIdx.x) >> 5;
    int lane = threadIdx.x & 31;
    if (n >= M) return;
    int start = g_row[n], end = g_row[n + 1];
    int h = lane & 7, slot = lane >> 3;            // 4 edge slots x 8 heads
    float ad = g_ad1[n * 8 + h];
    float mx = __int_as_float(0xff800000);
    for (int p = start + slot; p < end; p += 4) {
        float v = g_as1[g_csrc[p] * 8 + h] + ad;
        v = v >= 0.f ? v : NEG * v;
        mx = fmaxf(mx, v);
    }
    mx = fmaxf(mx, __shfl_xor_sync(0xffffffffu, mx, 8));
    mx = fmaxf(mx, __shfl_xor_sync(0xffffffffu, mx, 16));
    float den = 0.f;
    for (int p = start + slot; p < end; p += 4) {
        float v = g_as1[g_csrc[p] * 8 + h] + ad;
        v = v >= 0.f ? v : NEG * v;
        float ex = expf(v - mx);
        g_ex1[(size_t)p * 8 + h] = ex;
        den += ex;
    }
    den += __shfl_xor_sync(0xffffffffu, den, 8);
    den += __shfl_xor_sync(0xffffffffu, den, 16);
    if (slot == 0) g_inv1[n * 8 + h] = 1.f / den;  // every node has a self loop
}

// ---------------- layer1 aggregation: block per dst node, plain stores ----------
__global__ void __launch_bounds__(128) k_aggr1(float* __restrict__ emb,
                                               const float* __restrict__ b1) {
    int n = blockIdx.x;
    int t = threadIdx.x;
    __shared__ float sinv[8];
    if (t < 8) sinv[t] = g_inv1[n * 8 + t];
    __syncthreads();
    int start = g_row[n], end = g_row[n + 1];
    int h = t >> 4;
    float inv = sinv[h];
    float4 acc = make_float4(0.f, 0.f, 0.f, 0.f);
    for (int p = start; p < end; p++) {
        int s = g_csrc[p];
        float a = g_ex1[(size_t)p * 8 + h] * inv;
        float4 hv = ((const float4*)(g_h1 + (size_t)s * HHC))[t];
        acc.x += a * hv.x; acc.y += a * hv.y; acc.z += a * hv.z; acc.w += a * hv.w;
    }
    float4 bv = ((const float4*)b1)[t];
    acc.x += bv.x; acc.y += bv.y; acc.z += bv.z; acc.w += bv.w;
    ((float4*)(emb + (size_t)n * HHC))[t] = acc;
    float4 e;
    e.x = acc.x > 0.f ? acc.x : expm1f(acc.x);
    e.y = acc.y > 0.f ? acc.y : expm1f(acc.y);
    e.z = acc.z > 0.f ? acc.z : expm1f(acc.z);
    e.w = acc.w > 0.f ? acc.w : expm1f(acc.w);
    ((float4*)(g_hact + (size_t)n * HHC))[t] = e;
}

// ---------------- GEMM2 ----------------
__global__ void k_gemm2(const float* __restrict__ W2, int M) {
    __shared__ float Ws[NFEAT * NCLS];
    for (int i = threadIdx.x; i < NFEAT * NCLS; i += 256) Ws[i] = W2[i];
    __syncthreads();
    int c = threadIdx.x & 15;
    int n = blockIdx.x * 16 + (threadIdx.x >> 4);
    if (n >= M) return;
    const float4* hr4 = (const float4*)(g_hact + (size_t)n * HHC);
    float acc = 0.f;
#pragma unroll 8
    for (int k4 = 0; k4 < NFEAT / 4; k4++) {
        float4 hv = hr4[k4];
        int k = k4 * 4;
        acc += hv.x * Ws[(k + 0) * NCLS + c];
        acc += hv.y * Ws[(k + 1) * NCLS + c];
        acc += hv.z * Ws[(k + 2) * NCLS + c];
        acc += hv.w * Ws[(k + 3) * NCLS + c];
    }
    g_h2[(size_t)n * NCLS + c] = acc;
}

// ---------------- alpha2 ----------------
__global__ void k_alpha2(const float* __restrict__ asrc, const float* __restrict__ adst, int M) {
    int n = blockIdx.x * blockDim.x + threadIdx.x;
    if (n >= M) return;
    const float* hr = g_h2 + (size_t)n * NCLS;
    float sa = 0.f, sd = 0.f;
#pragma unroll
    for (int c = 0; c < NCLS; c++) {
        float v = hr[c];
        sa += v * asrc[c];
        sd += v * adst[c];
    }
    g_as2[n] = sa; g_ad2[n] = sd;
}

// ---------------- layer2 softmax: warp per dst node ----------------
__global__ void k_soft2(int M) {
    int n = (blockIdx.x * blockDim.x + threadIdx.x) >> 5;
    int lane = threadIdx.x & 31;
    if (n >= M) return;
    int start = g_row[n], end = g_row[n + 1];
    float ad = g_ad2[n];
    float mx = __int_as_float(0xff800000);
    for (int p = start + lane; p < end; p += 32) {
        float v = g_as2[g_csrc[p]] + ad;
        v = v >= 0.f ? v : NEG * v;
        mx = fmaxf(mx, v);
    }
#pragma unroll
    for (int o = 16; o; o >>= 1) mx = fmaxf(mx, __shfl_xor_sync(0xffffffffu, mx, o));
    float den = 0.f;
    for (int p = start + lane; p < end; p += 32) {
        float v = g_as2[g_csrc[p]] + ad;
        v = v >= 0.f ? v : NEG * v;
        float ex = expf(v - mx);
        g_ex2[p] = ex;
        den += ex;
    }
#pragma unroll
    for (int o = 16; o; o >>= 1) den += __shfl_xor_sync(0xffffffffu, den, o);
    if (lane == 0) g_inv2[n] = 1.f / den;
}

// ---------------- layer2 aggregation: 16 threads per node ----------------
__global__ void k_aggr2(float* __restrict__ logits, const float* __restrict__ b2, int M) {
    int n = blockIdx.x * 8 + (threadIdx.x >> 4);
    int c = threadIdx.x & 15;
    if (n >= M) return;
    int start = g_row[n], end = g_row[n + 1];
    float inv = g_inv2[n];
    float acc = 0.f;
    for (int p = start; p < end; p++) {
        float a = g_ex2[p] * inv;
        acc += a * g_h2[(size_t)g_csrc[p] * NCLS + c];
    }
    logits[(size_t)n * NCLS + c] = acc + b2[c];
}

// ---------------- launch ----------------
extern "C" void kernel_launch(void* const* d_in, const int* in_sizes, int n_in,
                              void* d_out, int out_size) {
    const float* x     = (const float*)d_in[0];
    const void*  ei    = d_in[1];
    const float* w1    = (const float*)d_in[2];
    const float* asrc1 = (const float*)d_in[3];
    const float* adst1 = (const float*)d_in[4];
    const float* b1    = (const float*)d_in[5];
    const float* w2    = (const float*)d_in[6];
    const float* asrc2 = (const float*)d_in[7];
    const float* adst2 = (const float*)d_in[8];
    const float* b2    = (const float*)d_in[9];

    const int M  = in_sizes[0] / NFEAT;     // 50000
    const int E  = in_sizes[1] / 2;         // 800000
    const int EN = E + M;                   // 850000

    float* logits = (float*)d_out;
    float* emb    = logits + (size_t)M * NCLS;

    // edges -> int32 src/dst with self loops, then CSR grouped by dst
    k_detect<<<1, 256>>>((const unsigned int*)ei);
    k_convert<<<(EN + 255) / 256, 256>>>(ei, E, EN);
    k_init0<<<(M + 255) / 256, 256>>>(M);
    k_count<<<(EN + 255) / 256, 256>>>(EN);
    k_scan<<<1, 1024>>>(M);
    k_scatter<<<(EN + 255) / 256, 256>>>(EN);

    // layer 1
    {
        dim3 grid(HHC / 128, (M + 127) / 128);
        k_gemm1<<<grid, 256>>>(x, w1, M);
    }
    k_alpha1<<<((M * 32) + 255) / 256, 256>>>(asrc1, adst1, M);
    k_soft1<<<((M * 32) + 255) / 256, 256>>>(M);
    k_aggr1<<<M, 128>>>(emb, b1);

    // layer 2
    k_gemm2<<<(M + 15) / 16, 256>>>(w2, M);
    k_alpha2<<<(M + 255) / 256, 256>>>(asrc2, adst2, M);
    k_soft2<<<((M * 32) + 255) / 256, 256>>>(M);
    k_aggr2<<<(M + 7) / 8, 128>>>(logits, b2, M);
}

// round 6
// speedup vs baseline: 3.1923x; 1.4522x over previous
#include <cuda_runtime.h>
#include <cuda_bf16.h>
#include <math.h>
#include <stdint.h>

#define NNODES 50000
#define NFEAT  512
#define HHC    512
#define NHEAD  8
#define NCLS   16
#define NEG    0.2f
#define MAXEN  850000

// ---------------- scratch ----------------
__device__ float g_h1  [(size_t)NNODES * HHC];
__device__ float g_hact[(size_t)NNODES * HHC];
__device__ float g_h2  [(size_t)NNODES * NCLS];
__device__ float g_w1t [NFEAT * HHC];        // W1 transposed: [N=512][K=512]
__device__ float g_as1[NNODES * NHEAD];
__device__ float g_ad1[NNODES * NHEAD];
__device__ float g_inv1[NNODES * NHEAD];
__device__ float g_as2[NNODES];
__device__ float g_ad2[NNODES];
__device__ float g_inv2[NNODES];
__device__ float g_ex1[(size_t)MAXEN * NHEAD];
__device__ float g_ex2[MAXEN];
__device__ int   g_src[MAXEN];
__device__ int   g_dst[MAXEN];
__device__ int   g_csrc[MAXEN];
__device__ int   g_row[NNODES + 1];
__device__ int   g_deg[NNODES];
__device__ int   g_fill[NNODES];
__device__ int   g_is64;

// ---------------- helpers ----------------
__device__ __forceinline__ uint32_t smem_u32(const void* p) {
    uint32_t a;
    asm("{ .reg .u64 t; cvta.to.shared.u64 t, %1; cvt.u32.u64 %0, t; }" : "=r"(a) : "l"(p));
    return a;
}
__device__ __forceinline__ void ldsm4(uint32_t addr, uint32_t* r) {
    asm volatile("ldmatrix.sync.aligned.m8n8.x4.shared.b16 {%0,%1,%2,%3}, [%4];"
                 : "=r"(r[0]), "=r"(r[1]), "=r"(r[2]), "=r"(r[3]) : "r"(addr));
}
#define MMA_BF16(c, a, b0, b1) \
    asm volatile("mma.sync.aligned.m16n8k16.row.col.f32.bf16.bf16.f32 " \
        "{%0,%1,%2,%3}, {%4,%5,%6,%7}, {%8,%9}, {%0,%1,%2,%3};" \
        : "+f"((c)[0]), "+f"((c)[1]), "+f"((c)[2]), "+f"((c)[3]) \
        : "r"((a)[0]), "r"((a)[1]), "r"((a)[2]), "r"((a)[3]), "r"(b0), "r"(b1))

__device__ __forceinline__ void split2(float a, float b, uint32_t& h, uint32_t& l) {
    __nv_bfloat16 ah = __float2bfloat16_rn(a), bh = __float2bfloat16_rn(b);
    float ar = a - __bfloat162float(ah), br = b - __bfloat162float(bh);
    __nv_bfloat16 al = __float2bfloat16_rn(ar), bl = __float2bfloat16_rn(br);
    h = (uint32_t)__bfloat16_as_ushort(ah) | ((uint32_t)__bfloat16_as_ushort(bh) << 16);
    l = (uint32_t)__bfloat16_as_ushort(al) | ((uint32_t)__bfloat16_as_ushort(bl) << 16);
}

// ---------------- edge dtype sniff + canonicalization ----------------
__global__ void k_detect(const unsigned int* __restrict__ ei32) {
    __shared__ int nz;
    if (threadIdx.x == 0) nz = 0;
    __syncthreads();
    for (int i = threadIdx.x; i < 4096; i += blockDim.x)
        if (ei32[2 * i + 1] != 0u) atomicOr(&nz, 1);
    __syncthreads();
    if (threadIdx.x == 0) g_is64 = nz ? 0 : 1;
}

__global__ void k_convert(const void* __restrict__ ei, int E, int EN) {
    int e = blockIdx.x * blockDim.x + threadIdx.x;
    if (e >= EN) return;
    int s, d;
    if (e < E) {
        if (g_is64) {
            const long long* p = (const long long*)ei;
            s = (int)p[e]; d = (int)p[(size_t)E + e];
        } else {
            const int* p = (const int*)ei;
            s = p[e]; d = p[E + e];
        }
    } else { s = e - E; d = e - E; }
    g_src[e] = s; g_dst[e] = d;
}

// ---------------- W1 transpose ----------------
__global__ void k_transpose(const float* __restrict__ w1) {
    __shared__ float t[32][33];
    int bx = blockIdx.x * 32, by = blockIdx.y * 32;
#pragma unroll
    for (int j = 0; j < 32; j += 8)
        t[threadIdx.y + j][threadIdx.x] = w1[(size_t)(by + threadIdx.y + j) * HHC + bx + threadIdx.x];
    __syncthreads();
#pragma unroll
    for (int j = 0; j < 32; j += 8)
        g_w1t[(size_t)(bx + threadIdx.y + j) * NFEAT + by + threadIdx.x] =
            t[threadIdx.x][threadIdx.y + j];
}

// ---------------- GEMM1: bf16 3-way split mma.sync ----------------
// Block 128x128, 8 warps (2m x 4n), warp tile 64x32, k-tile 16, double buffer.
__global__ void __launch_bounds__(256, 1) k_gemm1_mma(const float* __restrict__ A, int M) {
    __shared__ __align__(16) uint8_t sAh[2][6144], sAl[2][6144];
    __shared__ __align__(16) uint8_t sBh[2][6144], sBl[2][6144];
    int tid = threadIdx.x, lane = tid & 31, wid = tid >> 5;
    int warp_m = wid & 1, warp_n = wid >> 1;
    int rowBase = blockIdx.y << 7, colBase = blockIdx.x << 7;

    // ldg indices: 2 threads per row, 8 k each
    int ldRow = tid >> 1, ldK8 = (tid & 1) << 3;
    bool aValid = (rowBase + ldRow) < M;
    const float* Ap = A + (size_t)(rowBase + ldRow) * NFEAT + ldK8;
    const float* Bp = g_w1t + (size_t)(colBase + ldRow) * NFEAT + ldK8;
    int stOff = ldRow * 48 + ((tid & 1) << 4);

    // ldmatrix per-lane offsets
    uint32_t aOff[4], bOff[2];
#pragma unroll
    for (int mt = 0; mt < 4; mt++)
        aOff[mt] = (uint32_t)((warp_m * 64 + mt * 16 + (lane & 15)) * 48 + (((lane >> 4) & 1) << 4));
    {
        int b_n = (lane & 7) | ((lane & 16) >> 1);
        int b_kb = (lane & 8) << 1;
#pragma unroll
        for (int bt = 0; bt < 2; bt++)
            bOff[bt] = (uint32_t)((warp_n * 32 + bt * 16 + b_n) * 48 + b_kb);
    }
    uint32_t uAh = smem_u32(sAh), uAl = smem_u32(sAl);
    uint32_t uBh = smem_u32(sBh), uBl = smem_u32(sBl);

    float c[4][4][4];
#pragma unroll
    for (int i = 0; i < 4; i++)
#pragma unroll
        for (int j = 0; j < 4; j++)
#pragma unroll
            for (int q = 0; q < 4; q++) c[i][j][q] = 0.f;

    const float4 z4 = make_float4(0.f, 0.f, 0.f, 0.f);
    float4 ra0, ra1, rb0, rb1;
    // prologue load k-tile 0
    ra0 = aValid ? *(const float4*)(Ap + 0) : z4;
    ra1 = aValid ? *(const float4*)(Ap + 4) : z4;
    rb0 = *(const float4*)(Bp + 0);
    rb1 = *(const float4*)(Bp + 4);

    auto sts = [&](int buf, float4 a0, float4 a1, float4 b0, float4 b1) {
        uint4 H, L;
        split2(a0.x, a0.y, H.x, L.x); split2(a0.z, a0.w, H.y, L.y);
        split2(a1.x, a1.y, H.z, L.z); split2(a1.z, a1.w, H.w, L.w);
        *(uint4*)&sAh[buf][stOff] = H;
        *(uint4*)&sAl[buf][stOff] = L;
        split2(b0.x, b0.y, H.x, L.x); split2(b0.z, b0.w, H.y, L.y);
        split2(b1.x, b1.y, H.z, L.z); split2(b1.z, b1.w, H.w, L.w);
        *(uint4*)&sBh[buf][stOff] = H;
        *(uint4*)&sBl[buf][stOff] = L;
    };

    sts(0, ra0, ra1, rb0, rb1);
    __syncthreads();

    const int NT = NFEAT / 16;   // 32
    for (int kt = 0; kt < NT; kt++) {
        int buf = kt & 1;
        if (kt + 1 < NT) {
            int k = (kt + 1) * 16;
            ra0 = aValid ? *(const float4*)(Ap + k) : z4;
            ra1 = aValid ? *(const float4*)(Ap + k + 4) : z4;
            rb0 = *(const float4*)(Bp + k);
            rb1 = *(const float4*)(Bp + k + 4);
        }
        // fragments
        uint32_t ah[4][4], al[4][4], bh[2][4], bl[2][4];
        uint32_t bufOff = (uint32_t)buf * 6144;
#pragma unroll
        for (int mt = 0; mt < 4; mt++) {
            ldsm4(uAh + bufOff + aOff[mt], ah[mt]);
            ldsm4(uAl + bufOff + aOff[mt], al[mt]);
        }
#pragma unroll
        for (int bt = 0; bt < 2; bt++) {
            ldsm4(uBh + bufOff + bOff[bt], bh[bt]);
            ldsm4(uBl + bufOff + bOff[bt], bl[bt]);
        }
#pragma unroll
        for (int mt = 0; mt < 4; mt++)
#pragma unroll
            for (int nt = 0; nt < 4; nt++) {
                int bi = nt >> 1, bj = (nt & 1) << 1;
                MMA_BF16(c[mt][nt], ah[mt], bh[bi][bj], bh[bi][bj + 1]);
                MMA_BF16(c[mt][nt], ah[mt], bl[bi][bj], bl[bi][bj + 1]);
                MMA_BF16(c[mt][nt], al[mt], bh[bi][bj], bh[bi][bj + 1]);
            }
        if (kt + 1 < NT) sts((kt + 1) & 1, ra0, ra1, rb0, rb1);
        __syncthreads();
    }

    // epilogue
#pragma unroll
    for (int mt = 0; mt < 4; mt++) {
        int r0 = rowBase + warp_m * 64 + mt * 16 + (lane >> 2);
#pragma unroll
        for (int nt = 0; nt < 4; nt++) {
            int col = colBase + warp_n * 32 + nt * 8 + ((lane & 3) << 1);
            if (r0 < M)
                *(float2*)&g_h1[(size_t)r0 * HHC + col] = make_float2(c[mt][nt][0], c[mt][nt][1]);
            if (r0 + 8 < M)
                *(float2*)&g_h1[(size_t)(r0 + 8) * HHC + col] = make_float2(c[mt][nt][2], c[mt][nt][3]);
        }
    }
}

// ---------------- CSR build ----------------
__global__ void k_init0(int M) {
    int i = blockIdx.x * blockDim.x + threadIdx.x;
    if (i < M) { g_deg[i] = 0; g_fill[i] = 0; }
}
__global__ void k_count(int EN) {
    int e = blockIdx.x * blockDim.x + threadIdx.x;
    if (e < EN) atomicAdd(&g_deg[g_dst[e]], 1);
}
__global__ void k_scan(int M) {
    __shared__ int ss[1024];
    int t = threadIdx.x;
    int CH = (M + 1023) >> 10;
    int base = t * CH;
    int sum = 0;
    for (int i = 0; i < CH; i++) { int idx = base + i; if (idx < M) sum += g_deg[idx]; }
    ss[t] = sum; __syncthreads();
    for (int off = 1; off < 1024; off <<= 1) {
        int v = (t >= off) ? ss[t - off] : 0;
        __syncthreads();
        ss[t] += v;
        __syncthreads();
    }
    int off = (t == 0) ? 0 : ss[t - 1];
    for (int i = 0; i < CH; i++) {
        int idx = base + i;
        if (idx < M) { g_row[idx] = off; off += g_deg[idx]; }
    }
    if (t == 1023) g_row[M] = ss[1023];
}
__global__ void k_scatter(int EN) {
    int e = blockIdx.x * blockDim.x + threadIdx.x;
    if (e >= EN) return;
    int d = g_dst[e];
    int p = g_row[d] + atomicAdd(&g_fill[d], 1);
    g_csrc[p] = g_src[e];
}

// ---------------- alpha1 ----------------
__global__ void k_alpha1(const float* __restrict__ asrc, const float* __restrict__ adst, int M) {
    int gw = (blockIdx.x * blockDim.x + threadIdx.x) >> 5;
    int lane = threadIdx.x & 31;
    if (gw >= M) return;
    const float* hr = g_h1 + (size_t)gw * HHC;
#pragma unroll
    for (int h = 0; h < NHEAD; h++) {
        float v0 = hr[h * 64 + lane], v1 = hr[h * 64 + 32 + lane];
        float sa = v0 * asrc[h * 64 + lane] + v1 * asrc[h * 64 + 32 + lane];
        float sd = v0 * adst[h * 64 + lane] + v1 * adst[h * 64 + 32 + lane];
#pragma unroll
        for (int o = 16; o; o >>= 1) {
            sa += __shfl_down_sync(0xffffffffu, sa, o);
            sd += __shfl_down_sync(0xffffffffu, sd, o);
        }
        if (lane == 0) { g_as1[gw * 8 + h] = sa; g_ad1[gw * 8 + h] = sd; }
    }
}

// ---------------- layer1 softmax ----------------
__global__ void k_soft1(int M) {
    int n = (blockIdx.x * blockDim.x + threadIdx.x) >> 5;
    int lane = threadIdx.x & 31;
    if (n >= M) return;
    int start = g_row[n], end = g_row[n + 1];
    int h = lane & 7, slot = lane >> 3;
    float ad = g_ad1[n * 8 + h];
    float mx = __int_as_float(0xff800000);
    for (int p = start + slot; p < end; p += 4) {
        float v = g_as1[g_csrc[p] * 8 + h] + ad;
        v = v >= 0.f ? v : NEG * v;
        mx = fmaxf(mx, v);
    }
    mx = fmaxf(mx, __shfl_xor_sync(0xffffffffu, mx, 8));
    mx = fmaxf(mx, __shfl_xor_sync(0xffffffffu, mx, 16));
    float den = 0.f;
    for (int p = start + slot; p < end; p += 4) {
        float v = g_as1[g_csrc[p] * 8 + h] + ad;
        v = v >= 0.f ? v : NEG * v;
        float ex = expf(v - mx);
        g_ex1[(size_t)p * 8 + h] = ex;
        den += ex;
    }
    den += __shfl_xor_sync(0xffffffffu, den, 8);
    den += __shfl_xor_sync(0xffffffffu, den, 16);
    if (slot == 0) g_inv1[n * 8 + h] = 1.f / den;
}

// ---------------- layer1 aggregation ----------------
__global__ void __launch_bounds__(128) k_aggr1(float* __restrict__ emb,
                                               const float* __restrict__ b1) {
    int n = blockIdx.x;
    int t = threadIdx.x;
    __shared__ float sinv[8];
    if (t < 8) sinv[t] = g_inv1[n * 8 + t];
    __syncthreads();
    int start = g_row[n], end = g_row[n + 1];
    int h = t >> 4;
    float inv = sinv[h];
    float4 acc = make_float4(0.f, 0.f, 0.f, 0.f);
    for (int p = start; p < end; p++) {
        int s = g_csrc[p];
        float a = g_ex1[(size_t)p * 8 + h] * inv;
        float4 hv = ((const float4*)(g_h1 + (size_t)s * HHC))[t];
        acc.x += a * hv.x; acc.y += a * hv.y; acc.z += a * hv.z; acc.w += a * hv.w;
    }
    float4 bv = ((const float4*)b1)[t];
    acc.x += bv.x; acc.y += bv.y; acc.z += bv.z; acc.w += bv.w;
    ((float4*)(emb + (size_t)n * HHC))[t] = acc;
    float4 e;
    e.x = acc.x > 0.f ? acc.x : expm1f(acc.x);
    e.y = acc.y > 0.f ? acc.y : expm1f(acc.y);
    e.z = acc.z > 0.f ? acc.z : expm1f(acc.z);
    e.w = acc.w > 0.f ? acc.w : expm1f(acc.w);
    ((float4*)(g_hact + (size_t)n * HHC))[t] = e;
}

// ---------------- GEMM2 + alpha2 (fused) ----------------
__global__ void k_gemm2(const float* __restrict__ W2, const float* __restrict__ asrc,
                        const float* __restrict__ adst, int M) {
    __shared__ float Ws[NFEAT * NCLS];
    for (int i = threadIdx.x; i < NFEAT * NCLS; i += 256) Ws[i] = W2[i];
    __syncthreads();
    int c = threadIdx.x & 15;
    int n = blockIdx.x * 16 + (threadIdx.x >> 4);
    if (n >= M) return;
    const float4* hr4 = (const float4*)(g_hact + (size_t)n * HHC);
    float acc = 0.f;
#pragma unroll 8
    for (int k4 = 0; k4 < NFEAT / 4; k4++) {
        float4 hv = hr4[k4];
        int k = k4 * 4;
        acc += hv.x * Ws[(k + 0) * NCLS + c];
        acc += hv.y * Ws[(k + 1) * NCLS + c];
        acc += hv.z * Ws[(k + 2) * NCLS + c];
        acc += hv.w * Ws[(k + 3) * NCLS + c];
    }
    g_h2[(size_t)n * NCLS + c] = acc;
    float sa = acc * asrc[c], sd = acc * adst[c];
#pragma unroll
    for (int o = 8; o; o >>= 1) {
        sa += __shfl_xor_sync(0xffffffffu, sa, o);
        sd += __shfl_xor_sync(0xffffffffu, sd, o);
    }
    if (c == 0) { g_as2[n] = sa; g_ad2[n] = sd; }
}

// ---------------- layer2 softmax ----------------
__global__ void k_soft2(int M) {
    int n = (blockIdx.x * blockDim.x + threadIdx.x) >> 5;
    int lane = threadIdx.x & 31;
    if (n >= M) return;
    int start = g_row[n], end = g_row[n + 1];
    float ad = g_ad2[n];
    float mx = __int_as_float(0xff800000);
    for (int p = start + lane; p < end; p += 32) {
        float v = g_as2[g_csrc[p]] + ad;
        v = v >= 0.f ? v : NEG * v;
        mx = fmaxf(mx, v);
    }
#pragma unroll
    for (int o = 16; o; o >>= 1) mx = fmaxf(mx, __shfl_xor_sync(0xffffffffu, mx, o));
    float den = 0.f;
    for (int p = start + lane; p < end; p += 32) {
        float v = g_as2[g_csrc[p]] + ad;
        v = v >= 0.f ? v : NEG * v;
        float ex = expf(v - mx);
        g_ex2[p] = ex;
        den += ex;
    }
#pragma unroll
    for (int o = 16; o; o >>= 1) den += __shfl_xor_sync(0xffffffffu, den, o);
    if (lane == 0) g_inv2[n] = 1.f / den;
}

// ---------------- layer2 aggregation ----------------
__global__ void k_aggr2(float* __restrict__ logits, const float* __restrict__ b2, int M) {
    int n = blockIdx.x * 8 + (threadIdx.x >> 4);
    int c = threadIdx.x & 15;
    if (n >= M) return;
    int start = g_row[n], end = g_row[n + 1];
    float inv = g_inv2[n];
    float acc = 0.f;
    for (int p = start; p < end; p++) {
        float a = g_ex2[p] * inv;
        acc += a * g_h2[(size_t)g_csrc[p] * NCLS + c];
    }
    logits[(size_t)n * NCLS + c] = acc + b2[c];
}

// ---------------- launch ----------------
extern "C" void kernel_launch(void* const* d_in, const int* in_sizes, int n_in,
                              void* d_out, int out_size) {
    const float* x     = (const float*)d_in[0];
    const void*  ei    = d_in[1];
    const float* w1    = (const float*)d_in[2];
    const float* asrc1 = (const float*)d_in[3];
    const float* adst1 = (const float*)d_in[4];
    const float* b1    = (const float*)d_in[5];
    const float* w2    = (const float*)d_in[6];
    const float* asrc2 = (const float*)d_in[7];
    const float* adst2 = (const float*)d_in[8];
    const float* b2    = (const float*)d_in[9];

    const int M  = in_sizes[0] / NFEAT;     // 50000
    const int E  = in_sizes[1] / 2;         // 800000
    const int EN = E + M;                   // 850000

    float* logits = (float*)d_out;
    float* emb    = logits + (size_t)M * NCLS;

    // launch index 3 = the mma GEMM, so ncu profiles it
    k_detect<<<1, 256>>>((const unsigned int*)ei);
    k_convert<<<(EN + 255) / 256, 256>>>(ei, E, EN);
    {
        dim3 g(16, 16), b(32, 8);
        k_transpose<<<g, b>>>(w1);
    }
    {
        dim3 grid(HHC / 128, (M + 127) / 128);
        k_gemm1_mma<<<grid, 256>>>(x, M);
    }
    // CSR build
    k_init0<<<(M + 255) / 256, 256>>>(M);
    k_count<<<(EN + 255) / 256, 256>>>(EN);
    k_scan<<<1, 1024>>>(M);
    k_scatter<<<(EN + 255) / 256, 256>>>(EN);

    k_alpha1<<<((M * 32) + 255) / 256, 256>>>(asrc1, adst1, M);
    k_soft1<<<((M * 32) + 255) / 256, 256>>>(M);
    k_aggr1<<<M, 128>>>(emb, b1);

    k_gemm2<<<(M + 15) / 16, 256>>>(w2, asrc2, adst2, M);
    k_soft2<<<((M * 32) + 255) / 256, 256>>>(M);
    k_aggr2<<<(M + 7) / 8, 128>>>(logits, b2, M);
}

// round 8
// speedup vs baseline: 3.5853x; 1.1231x over previous
#include <cuda_runtime.h>
#include <cuda_bf16.h>
#include <math.h>
#include <stdint.h>

#define NNODES 50000
#define NFEAT  512
#define HHC    512
#define NHEAD  8
#define NCLS   16
#define NEG    0.2f
#define MAXEN  850000

// GEMM1 smem staging: 4 regions (Ah, Al, Bh, Bl) x 128 rows x 48B pitch
#define ROWS_B    48
#define REGION    (128 * ROWS_B)     // 6144
#define OFF_AL    REGION
#define OFF_BH    (2 * REGION)
#define OFF_BL    (3 * REGION)
#define STG_BYTES (4 * REGION)       // 24576 per stage
#define DSMEM_G1  (3 * STG_BYTES)    // 73728

// ---------------- scratch ----------------
__device__ float g_h1  [(size_t)NNODES * HHC];
__device__ float g_hact[(size_t)NNODES * HHC];
__device__ float g_h2  [(size_t)NNODES * NCLS];
__device__ __nv_bfloat16 g_xh[(size_t)NNODES * NFEAT];
__device__ __nv_bfloat16 g_xl[(size_t)NNODES * NFEAT];
__device__ __nv_bfloat16 g_wth[NFEAT * HHC];   // W1^T hi: [n][k]
__device__ __nv_bfloat16 g_wtl[NFEAT * HHC];   // W1^T lo
__device__ float g_as1[NNODES * NHEAD];
__device__ float g_ad1[NNODES * NHEAD];
__device__ float g_inv1[NNODES * NHEAD];
__device__ float g_as2[NNODES];
__device__ float g_ad2[NNODES];
__device__ float g_inv2[NNODES];
__device__ float g_ex1[(size_t)MAXEN * NHEAD];
__device__ float g_ex2[MAXEN];
__device__ int   g_src[MAXEN];
__device__ int   g_dst[MAXEN];
__device__ int   g_csrc[MAXEN];
__device__ int   g_row[NNODES + 1];
__device__ int   g_deg[NNODES];
__device__ int   g_fill[NNODES];
__device__ int   g_is64;

// ---------------- helpers ----------------
__device__ __forceinline__ uint32_t smem_u32(const void* p) {
    uint32_t a;
    asm("{ .reg .u64 t; cvta.to.shared.u64 t, %1; cvt.u32.u64 %0, t; }" : "=r"(a) : "l"(p));
    return a;
}
__device__ __forceinline__ void ldsm4(uint32_t addr, uint32_t* r) {
    asm volatile("ldmatrix.sync.aligned.m8n8.x4.shared.b16 {%0,%1,%2,%3}, [%4];"
                 : "=r"(r[0]), "=r"(r[1]), "=r"(r[2]), "=r"(r[3]) : "r"(addr));
}
#define MMA_BF16(c, a, b0, b1) \
    asm volatile("mma.sync.aligned.m16n8k16.row.col.f32.bf16.bf16.f32 " \
        "{%0,%1,%2,%3}, {%4,%5,%6,%7}, {%8,%9}, {%0,%1,%2,%3};" \
        : "+f"((c)[0]), "+f"((c)[1]), "+f"((c)[2]), "+f"((c)[3]) \
        : "r"((a)[0]), "r"((a)[1]), "r"((a)[2]), "r"((a)[3]), "r"(b0), "r"(b1))

#define CP16(dst, src, sz) \
    asm volatile("cp.async.cg.shared.global [%0], [%1], 16, %2;" \
                 :: "r"(dst), "l"(src), "r"(sz) : "memory")
#define CP_COMMIT() asm volatile("cp.async.commit_group;" ::: "memory")
#define CP_WAIT1()  asm volatile("cp.async.wait_group 1;" ::: "memory")

__device__ __forceinline__ void splitf(float a, __nv_bfloat16& h, __nv_bfloat16& l) {
    h = __float2bfloat16_rn(a);
    l = __float2bfloat16_rn(a - __bfloat162float(h));
}

// ---------------- split x -> bf16 hi/lo ----------------
__global__ void k_split_x(const float* __restrict__ x, size_t n4) {
    size_t i = (size_t)blockIdx.x * blockDim.x + threadIdx.x;
    if (i >= n4) return;
    float4 v = ((const float4*)x)[i];
    __nv_bfloat16 h0, h1, h2, h3, l0, l1, l2, l3;
    splitf(v.x, h0, l0); splitf(v.y, h1, l1);
    splitf(v.z, h2, l2); splitf(v.w, h3, l3);
    ushort4 H = make_ushort4(__bfloat16_as_ushort(h0), __bfloat16_as_ushort(h1),
                             __bfloat16_as_ushort(h2), __bfloat16_as_ushort(h3));
    ushort4 L = make_ushort4(__bfloat16_as_ushort(l0), __bfloat16_as_ushort(l1),
                             __bfloat16_as_ushort(l2), __bfloat16_as_ushort(l3));
    ((ushort4*)g_xh)[i] = H;
    ((ushort4*)g_xl)[i] = L;
}

// ---------------- W1 transpose + split ----------------
__global__ void k_split_wt(const float* __restrict__ w1) {
    __shared__ float t[32][33];
    int bx = blockIdx.x * 32, by = blockIdx.y * 32;
#pragma unroll
    for (int j = 0; j < 32; j += 8)
        t[threadIdx.y + j][threadIdx.x] = w1[(size_t)(by + threadIdx.y + j) * HHC + bx + threadIdx.x];
    __syncthreads();
#pragma unroll
    for (int j = 0; j < 32; j += 8) {
        float v = t[threadIdx.x][threadIdx.y + j];
        __nv_bfloat16 h, l;
        splitf(v, h, l);
        size_t o = (size_t)(bx + threadIdx.y + j) * NFEAT + by + threadIdx.x;
        g_wth[o] = h;
        g_wtl[o] = l;
    }
}

// ---------------- edge dtype sniff + canonicalization ----------------
__global__ void k_detect(const unsigned int* __restrict__ ei32) {
    __shared__ int nz;
    if (threadIdx.x == 0) nz = 0;
    __syncthreads();
    for (int i = threadIdx.x; i < 4096; i += blockDim.x)
        if (ei32[2 * i + 1] != 0u) atomicOr(&nz, 1);
    __syncthreads();
    if (threadIdx.x == 0) g_is64 = nz ? 0 : 1;
}

__global__ void k_convert(const void* __restrict__ ei, int E, int EN) {
    int e = blockIdx.x * blockDim.x + threadIdx.x;
    if (e >= EN) return;
    int s, d;
    if (e < E) {
        if (g_is64) {
            const long long* p = (const long long*)ei;
            s = (int)p[e]; d = (int)p[(size_t)E + e];
        } else {
            const int* p = (const int*)ei;
            s = p[e]; d = p[E + e];
        }
    } else { s = e - E; d = e - E; }
    g_src[e] = s; g_dst[e] = d;
}

// ---------------- GEMM1: pre-split bf16, cp.async 3-stage, 3-term mma ----------
// Block 128x128, 8 warps (2m x 4n), warp tile 64x32, k-tile 16.
__global__ void __launch_bounds__(256, 2) k_gemm1_mma(int M) {
    extern __shared__ __align__(16) uint8_t sm[];
    int tid = threadIdx.x, lane = tid & 31, wid = tid >> 5;
    int warp_m = wid & 1, warp_n = wid >> 1;
    int rowBase = blockIdx.y << 7, colBase = blockIdx.x << 7;
    uint32_t uS = smem_u32(sm);

    // cp.async indices: thread -> (row 0..127, 16B half)
    int cRow = tid >> 1, cHalf = tid & 1;
    uint32_t aSz = (rowBase + cRow) < M ? 16u : 0u;
    const __nv_bfloat16* Ah = g_xh + (size_t)(rowBase + cRow) * NFEAT + cHalf * 8;
    const __nv_bfloat16* Al = g_xl + (size_t)(rowBase + cRow) * NFEAT + cHalf * 8;
    const __nv_bfloat16* Bh = g_wth + (size_t)(colBase + cRow) * NFEAT + cHalf * 8;
    const __nv_bfloat16* Bl = g_wtl + (size_t)(colBase + cRow) * NFEAT + cHalf * 8;
    uint32_t cDst = (uint32_t)(cRow * ROWS_B + cHalf * 16);

    // ldmatrix per-lane offsets (relative to region base)
    uint32_t aRel[4], bRel[2];
#pragma unroll
    for (int mt = 0; mt < 4; mt++)
        aRel[mt] = (uint32_t)((warp_m * 64 + mt * 16 + (lane & 15)) * ROWS_B
                              + (((lane >> 4) & 1) << 4));
    {
        int b_n = (lane & 7) | ((lane & 16) >> 1);
        int b_kb = (lane & 8) << 1;
#pragma unroll
        for (int bt = 0; bt < 2; bt++)
            bRel[bt] = (uint32_t)((warp_n * 32 + bt * 16 + b_n) * ROWS_B + b_kb);
    }

    float c[4][4][4];
#pragma unroll
    for (int i = 0; i < 4; i++)
#pragma unroll
        for (int j = 0; j < 4; j++)
#pragma unroll
            for (int q = 0; q < 4; q++) c[i][j][q] = 0.f;

    auto issue = [&](int kt, int buf) {
        uint32_t b = uS + (uint32_t)buf * STG_BYTES + cDst;
        CP16(b,          Ah + kt * 16, aSz);
        CP16(b + OFF_AL, Al + kt * 16, aSz);
        CP16(b + OFF_BH, Bh + kt * 16, 16u);
        CP16(b + OFF_BL, Bl + kt * 16, 16u);
    };

    issue(0, 0); CP_COMMIT();
    issue(1, 1); CP_COMMIT();

    const int NT = NFEAT / 16;   // 32
    for (int kt = 0; kt < NT; kt++) {
        CP_WAIT1();
        __syncthreads();
        uint32_t base = uS + (uint32_t)(kt % 3) * STG_BYTES;

        uint32_t ah[4][4], bh[2][4];
#pragma unroll
        for (int mt = 0; mt < 4; mt++) ldsm4(base + aRel[mt], ah[mt]);
#pragma unroll
        for (int bt = 0; bt < 2; bt++) ldsm4(base + OFF_BH + bRel[bt], bh[bt]);
#pragma unroll
        for (int mt = 0; mt < 4; mt++)
#pragma unroll
            for (int nt = 0; nt < 4; nt++) {
                int bi = nt >> 1, bj = (nt & 1) << 1;
                MMA_BF16(c[mt][nt], ah[mt], bh[bi][bj], bh[bi][bj + 1]);
            }
        uint32_t bl[2][4];
#pragma unroll
        for (int bt = 0; bt < 2; bt++) ldsm4(base + OFF_BL + bRel[bt], bl[bt]);
#pragma unroll
        for (int mt = 0; mt < 4; mt++)
#pragma unroll
            for (int nt = 0; nt < 4; nt++) {
                int bi = nt >> 1, bj = (nt & 1) << 1;
                MMA_BF16(c[mt][nt], ah[mt], bl[bi][bj], bl[bi][bj + 1]);
            }
        uint32_t al[4][4];
#pragma unroll
        for (int mt = 0; mt < 4; mt++) ldsm4(base + OFF_AL + aRel[mt], al[mt]);
#pragma unroll
        for (int mt = 0; mt < 4; mt++)
#pragma unroll
            for (int nt = 0; nt < 4; nt++) {
                int bi = nt >> 1, bj = (nt & 1) << 1;
                MMA_BF16(c[mt][nt], al[mt], bh[bi][bj], bh[bi][bj + 1]);
            }

        if (kt + 2 < NT) issue(kt + 2, (kt + 2) % 3);
        CP_COMMIT();
    }

    // epilogue
#pragma unroll
    for (int mt = 0; mt < 4; mt++) {
        int r0 = rowBase + warp_m * 64 + mt * 16 + (lane >> 2);
#pragma unroll
        for (int nt = 0; nt < 4; nt++) {
            int col = colBase + warp_n * 32 + nt * 8 + ((lane & 3) << 1);
            if (r0 < M)
                *(float2*)&g_h1[(size_t)r0 * HHC + col] = make_float2(c[mt][nt][0], c[mt][nt][1]);
            if (r0 + 8 < M)
                *(float2*)&g_h1[(size_t)(r0 + 8) * HHC + col] = make_float2(c[mt][nt][2], c[mt][nt][3]);
        }
    }
}

// ---------------- CSR build ----------------
__global__ void k_init0(int M) {
    int i = blockIdx.x * blockDim.x + threadIdx.x;
    if (i < M) { g_deg[i] = 0; g_fill[i] = 0; }
}
__global__ void k_count(int EN) {
    int e = blockIdx.x * blockDim.x + threadIdx.x;
    if (e < EN) atomicAdd(&g_deg[g_dst[e]], 1);
}
__global__ void k_scan(int M) {
    __shared__ int ss[1024];
    int t = threadIdx.x;
    int CH = (M + 1023) >> 10;
    int base = t * CH;
    int sum = 0;
    for (int i = 0; i < CH; i++) { int idx = base + i; if (idx < M) sum += g_deg[idx]; }
    ss[t] = sum; __syncthreads();
    for (int off = 1; off < 1024; off <<= 1) {
        int v = (t >= off) ? ss[t - off] : 0;
        __syncthreads();
        ss[t] += v;
        __syncthreads();
    }
    int off = (t == 0) ? 0 : ss[t - 1];
    for (int i = 0; i < CH; i++) {
        int idx = base + i;
        if (idx < M) { g_row[idx] = off; off += g_deg[idx]; }
    }
    if (t == 1023) g_row[M] = ss[1023];
}
__global__ void k_scatter(int EN) {
    int e = blockIdx.x * blockDim.x + threadIdx.x;
    if (e >= EN) return;
    int d = g_dst[e];
    int p = g_row[d] + atomicAdd(&g_fill[d], 1);
    g_csrc[p] = g_src[e];
}

// ---------------- alpha1 ----------------
__global__ void k_alpha1(const float* __restrict__ asrc, const float* __restrict__ adst, int M) {
    int gw = (blockIdx.x * blockDim.x + threadIdx.x) >> 5;
    int lane = threadIdx.x & 31;
    if (gw >= M) return;
    const float* hr = g_h1 + (size_t)gw * HHC;
#pragma unroll
    for (int h = 0; h < NHEAD; h++) {
        float v0 = hr[h * 64 + lane], v1 = hr[h * 64 + 32 + lane];
        float sa = v0 * asrc[h * 64 + lane] + v1 * asrc[h * 64 + 32 + lane];
        float sd = v0 * adst[h * 64 + lane] + v1 * adst[h * 64 + 32 + lane];
#pragma unroll
        for (int o = 16; o; o >>= 1) {
            sa += __shfl_down_sync(0xffffffffu, sa, o);
            sd += __shfl_down_sync(0xffffffffu, sd, o);
        }
        if (lane == 0) { g_as1[gw * 8 + h] = sa; g_ad1[gw * 8 + h] = sd; }
    }
}

// ---------------- layer1 softmax ----------------
__global__ void k_soft1(int M) {
    int n = (blockIdx.x * blockDim.x + threadIdx.x) >> 5;
    int lane = threadIdx.x & 31;
    if (n >= M) return;
    int start = g_row[n], end = g_row[n + 1];
    int h = lane & 7, slot = lane >> 3;
    float ad = g_ad1[n * 8 + h];
    float mx = __int_as_float(0xff800000);
    for (int p = start + slot; p < end; p += 4) {
        float v = g_as1[g_csrc[p] * 8 + h] + ad;
        v = v >= 0.f ? v : NEG * v;
        mx = fmaxf(mx, v);
    }
    mx = fmaxf(mx, __shfl_xor_sync(0xffffffffu, mx, 8));
    mx = fmaxf(mx, __shfl_xor_sync(0xffffffffu, mx, 16));
    float den = 0.f;
    for (int p = start + slot; p < end; p += 4) {
        float v = g_as1[g_csrc[p] * 8 + h] + ad;
        v = v >= 0.f ? v : NEG * v;
        float ex = expf(v - mx);
        g_ex1[(size_t)p * 8 + h] = ex;
        den += ex;
    }
    den += __shfl_xor_sync(0xffffffffu, den, 8);
    den += __shfl_xor_sync(0xffffffffu, den, 16);
    if (slot == 0) g_inv1[n * 8 + h] = 1.f / den;
}

// ---------------- layer1 aggregation ----------------
__global__ void __launch_bounds__(128) k_aggr1(float* __restrict__ emb,
                                               const float* __restrict__ b1) {
    int n = blockIdx.x;
    int t = threadIdx.x;
    __shared__ float sinv[8];
    if (t < 8) sinv[t] = g_inv1[n * 8 + t];
    __syncthreads();
    int start = g_row[n], end = g_row[n + 1];
    int h = t >> 4;
    float inv = sinv[h];
    float4 acc = make_float4(0.f, 0.f, 0.f, 0.f);
    for (int p = start; p < end; p++) {
        int s = g_csrc[p];
        float a = g_ex1[(size_t)p * 8 + h] * inv;
        float4 hv = ((const float4*)(g_h1 + (size_t)s * HHC))[t];
        acc.x += a * hv.x; acc.y += a * hv.y; acc.z += a * hv.z; acc.w += a * hv.w;
    }
    float4 bv = ((const float4*)b1)[t];
    acc.x += bv.x; acc.y += bv.y; acc.z += bv.z; acc.w += bv.w;
    ((float4*)(emb + (size_t)n * HHC))[t] = acc;
    float4 e;
    e.x = acc.x > 0.f ? acc.x : expm1f(acc.x);
    e.y = acc.y > 0.f ? acc.y : expm1f(acc.y);
    e.z = acc.z > 0.f ? acc.z : expm1f(acc.z);
    e.w = acc.w > 0.f ? acc.w : expm1f(acc.w);
    ((float4*)(g_hact + (size_t)n * HHC))[t] = e;
}

// ---------------- GEMM2 + alpha2 (fused) ----------------
__global__ void k_gemm2(const float* __restrict__ W2, const float* __restrict__ asrc,
                        const float* __restrict__ adst, int M) {
    __shared__ float Ws[NFEAT * NCLS];
    for (int i = threadIdx.x; i < NFEAT * NCLS; i += 256) Ws[i] = W2[i];
    __syncthreads();
    int c = threadIdx.x & 15;
    int n = blockIdx.x * 16 + (threadIdx.x >> 4);
    if (n >= M) return;
    const float4* hr4 = (const float4*)(g_hact + (size_t)n * HHC);
    float acc = 0.f;
#pragma unroll 8
    for (int k4 = 0; k4 < NFEAT / 4; k4++) {
        float4 hv = hr4[k4];
        int k = k4 * 4;
        acc += hv.x * Ws[(k + 0) * NCLS + c];
        acc += hv.y * Ws[(k + 1) * NCLS + c];
        acc += hv.z * Ws[(k + 2) * NCLS + c];
        acc += hv.w * Ws[(k + 3) * NCLS + c];
    }
    g_h2[(size_t)n * NCLS + c] = acc;
    float sa = acc * asrc[c], sd = acc * adst[c];
#pragma unroll
    for (int o = 8; o; o >>= 1) {
        sa += __shfl_xor_sync(0xffffffffu, sa, o);
        sd += __shfl_xor_sync(0xffffffffu, sd, o);
    }
    if (c == 0) { g_as2[n] = sa; g_ad2[n] = sd; }
}

// ---------------- layer2 softmax ----------------
__global__ void k_soft2(int M) {
    int n = (blockIdx.x * blockDim.x + threadIdx.x) >> 5;
    int lane = threadIdx.x & 31;
    if (n >= M) return;
    int start = g_row[n], end = g_row[n + 1];
    float ad = g_ad2[n];
    float mx = __int_as_float(0xff800000);
    for (int p = start + lane; p < end; p += 32) {
        float v = g_as2[g_csrc[p]] + ad;
        v = v >= 0.f ? v : NEG * v;
        mx = fmaxf(mx, v);
    }
#pragma unroll
    for (int o = 16; o; o >>= 1) mx = fmaxf(mx, __shfl_xor_sync(0xffffffffu, mx, o));
    float den = 0.f;
    for (int p = start + lane; p < end; p += 32) {
        float v = g_as2[g_csrc[p]] + ad;
        v = v >= 0.f ? v : NEG * v;
        float ex = expf(v - mx);
        g_ex2[p] = ex;
        den += ex;
    }
#pragma unroll
    for (int o = 16; o; o >>= 1) den += __shfl_xor_sync(0xffffffffu, den, o);
    if (lane == 0) g_inv2[n] = 1.f / den;
}

// ---------------- layer2 aggregation ----------------
__global__ void k_aggr2(float* __restrict__ logits, const float* __restrict__ b2, int M) {
    int n = blockIdx.x * 8 + (threadIdx.x >> 4);
    int c = threadIdx.x & 15;
    if (n >= M) return;
    int start = g_row[n], end = g_row[n + 1];
    float inv = g_inv2[n];
    float acc = 0.f;
    for (int p = start; p < end; p++) {
        float a = g_ex2[p] * inv;
        acc += a * g_h2[(size_t)g_csrc[p] * NCLS + c];
    }
    logits[(size_t)n * NCLS + c] = acc + b2[c];
}

// ---------------- launch ----------------
extern "C" void kernel_launch(void* const* d_in, const int* in_sizes, int n_in,
                              void* d_out, int out_size) {
    const float* x     = (const float*)d_in[0];
    const void*  ei    = d_in[1];
    const float* w1    = (const float*)d_in[2];
    const float* asrc1 = (const float*)d_in[3];
    const float* adst1 = (const float*)d_in[4];
    const float* b1    = (const float*)d_in[5];
    const float* w2    = (const float*)d_in[6];
    const float* asrc2 = (const float*)d_in[7];
    const float* adst2 = (const float*)d_in[8];
    const float* b2    = (const float*)d_in[9];

    const int M  = in_sizes[0] / NFEAT;     // 50000
    const int E  = in_sizes[1] / 2;         // 800000
    const int EN = E + M;                   // 850000

    float* logits = (float*)d_out;
    float* emb    = logits + (size_t)M * NCLS;

    cudaFuncSetAttribute(k_gemm1_mma, cudaFuncAttributeMaxDynamicSharedMemorySize, DSMEM_G1);

    size_t n4 = (size_t)M * NFEAT / 4;
    k_split_x<<<(unsigned)((n4 + 255) / 256), 256>>>(x, n4);          // 0
    {
        dim3 g(16, 16), b(32, 8);
        k_split_wt<<<g, b>>>(w1);                                      // 1
    }
    k_detect<<<1, 256>>>((const unsigned int*)ei);                     // 2
    {
        dim3 grid(HHC / 128, (M + 127) / 128);
        k_gemm1_mma<<<grid, 256, DSMEM_G1>>>(M);                       // 3 (profiled)
    }
    k_convert<<<(EN + 255) / 256, 256>>>(ei, E, EN);
    k_init0<<<(M + 255) / 256, 256>>>(M);
    k_count<<<(EN + 255) / 256, 256>>>(EN);
    k_scan<<<1, 1024>>>(M);
    k_scatter<<<(EN + 255) / 256, 256>>>(EN);

    k_alpha1<<<((M * 32) + 255) / 256, 256>>>(asrc1, adst1, M);
    k_soft1<<<((M * 32) + 255) / 256, 256>>>(M);
    k_aggr1<<<M, 128>>>(emb, b1);

    k_gemm2<<<(M + 15) / 16, 256>>>(w2, asrc2, adst2, M);
    k_soft2<<<((M * 32) + 255) / 256, 256>>>(M);
    k_aggr2<<<(M + 7) / 8, 128>>>(logits, b2, M);
}

// round 9
// speedup vs baseline: 3.7006x; 1.0322x over previous
#include <cuda_runtime.h>
#include <cuda_bf16.h>
#include <cuda_fp16.h>
#include <math.h>
#include <stdint.h>

#define NNODES 50000
#define NFEAT  512
#define HHC    512
#define NHEAD  8
#define NCLS   16
#define NEG    0.2f
#define MAXEN  850000

// GEMM1 smem staging: 4 regions (Ah, Al, Bh, Bl) x 128 rows x 48B pitch
#define ROWS_B    48
#define REGION    (128 * ROWS_B)     // 6144
#define OFF_AL    REGION
#define OFF_BH    (2 * REGION)
#define OFF_BL    (3 * REGION)
#define STG_BYTES (4 * REGION)       // 24576 per stage
#define DSMEM_G1  (3 * STG_BYTES)    // 73728
#define GRID_G1   296                // persistent: 2 CTA/SM x 148

// ---------------- scratch ----------------
__device__ __half g_h1h [(size_t)NNODES * HHC];   // layer1 features, fp16
__device__ float g_hact[(size_t)NNODES * HHC];
__device__ float g_h2  [(size_t)NNODES * NCLS];
__device__ __nv_bfloat16 g_xh[(size_t)NNODES * NFEAT];
__device__ __nv_bfloat16 g_xl[(size_t)NNODES * NFEAT];
__device__ __nv_bfloat16 g_wth[NFEAT * HHC];   // W1^T hi: [n][k]
__device__ __nv_bfloat16 g_wtl[NFEAT * HHC];   // W1^T lo
__device__ float g_as1[NNODES * NHEAD];
__device__ float g_ad1[NNODES * NHEAD];
__device__ float g_inv1[NNODES * NHEAD];
__device__ float g_as2[NNODES];
__device__ float g_ad2[NNODES];
__device__ float g_inv2[NNODES];
__device__ float g_ex1[(size_t)MAXEN * NHEAD];
__device__ float g_ex2[MAXEN];
__device__ int   g_src[MAXEN];
__device__ int   g_dst[MAXEN];
__device__ int   g_csrc[MAXEN];
__device__ int   g_row[NNODES + 1];
__device__ int   g_deg[NNODES];
__device__ int   g_fill[NNODES];
__device__ int   g_is64;

// ---------------- helpers ----------------
__device__ __forceinline__ uint32_t smem_u32(const void* p) {
    uint32_t a;
    asm("{ .reg .u64 t; cvta.to.shared.u64 t, %1; cvt.u32.u64 %0, t; }" : "=r"(a) : "l"(p));
    return a;
}
__device__ __forceinline__ void ldsm4(uint32_t addr, uint32_t* r) {
    asm volatile("ldmatrix.sync.aligned.m8n8.x4.shared.b16 {%0,%1,%2,%3}, [%4];"
                 : "=r"(r[0]), "=r"(r[1]), "=r"(r[2]), "=r"(r[3]) : "r"(addr));
}
#define MMA_BF16(c, a, b0, b1) \
    asm volatile("mma.sync.aligned.m16n8k16.row.col.f32.bf16.bf16.f32 " \
        "{%0,%1,%2,%3}, {%4,%5,%6,%7}, {%8,%9}, {%0,%1,%2,%3};" \
        : "+f"((c)[0]), "+f"((c)[1]), "+f"((c)[2]), "+f"((c)[3]) \
        : "r"((a)[0]), "r"((a)[1]), "r"((a)[2]), "r"((a)[3]), "r"(b0), "r"(b1))

#define CP16(dst, src, sz) \
    asm volatile("cp.async.cg.shared.global [%0], [%1], 16, %2;" \
                 :: "r"(dst), "l"(src), "r"(sz) : "memory")
#define CP_COMMIT() asm volatile("cp.async.commit_group;" ::: "memory")
#define CP_WAIT1()  asm volatile("cp.async.wait_group 1;" ::: "memory")

__device__ __forceinline__ void splitf(float a, __nv_bfloat16& h, __nv_bfloat16& l) {
    h = __float2bfloat16_rn(a);
    l = __float2bfloat16_rn(a - __bfloat162float(h));
}

// ---------------- split x -> bf16 hi/lo ----------------
__global__ void k_split_x(const float* __restrict__ x, size_t n4) {
    size_t i = (size_t)blockIdx.x * blockDim.x + threadIdx.x;
    if (i >= n4) return;
    float4 v = ((const float4*)x)[i];
    __nv_bfloat16 h0, h1, h2, h3, l0, l1, l2, l3;
    splitf(v.x, h0, l0); splitf(v.y, h1, l1);
    splitf(v.z, h2, l2); splitf(v.w, h3, l3);
    ushort4 H = make_ushort4(__bfloat16_as_ushort(h0), __bfloat16_as_ushort(h1),
                             __bfloat16_as_ushort(h2), __bfloat16_as_ushort(h3));
    ushort4 L = make_ushort4(__bfloat16_as_ushort(l0), __bfloat16_as_ushort(l1),
                             __bfloat16_as_ushort(l2), __bfloat16_as_ushort(l3));
    ((ushort4*)g_xh)[i] = H;
    ((ushort4*)g_xl)[i] = L;
}

// ---------------- W1 transpose + split ----------------
__global__ void k_split_wt(const float* __restrict__ w1) {
    __shared__ float t[32][33];
    int bx = blockIdx.x * 32, by = blockIdx.y * 32;
#pragma unroll
    for (int j = 0; j < 32; j += 8)
        t[threadIdx.y + j][threadIdx.x] = w1[(size_t)(by + threadIdx.y + j) * HHC + bx + threadIdx.x];
    __syncthreads();
#pragma unroll
    for (int j = 0; j < 32; j += 8) {
        float v = t[threadIdx.x][threadIdx.y + j];
        __nv_bfloat16 h, l;
        splitf(v, h, l);
        size_t o = (size_t)(bx + threadIdx.y + j) * NFEAT + by + threadIdx.x;
        g_wth[o] = h;
        g_wtl[o] = l;
    }
}

// ---------------- edge dtype sniff + canonicalization ----------------
__global__ void k_detect(const unsigned int* __restrict__ ei32) {
    __shared__ int nz;
    if (threadIdx.x == 0) nz = 0;
    __syncthreads();
    for (int i = threadIdx.x; i < 4096; i += blockDim.x)
        if (ei32[2 * i + 1] != 0u) atomicOr(&nz, 1);
    __syncthreads();
    if (threadIdx.x == 0) g_is64 = nz ? 0 : 1;
}

__global__ void k_convert(const void* __restrict__ ei, int E, int EN) {
    int e = blockIdx.x * blockDim.x + threadIdx.x;
    if (e >= EN) return;
    int s, d;
    if (e < E) {
        if (g_is64) {
            const long long* p = (const long long*)ei;
            s = (int)p[e]; d = (int)p[(size_t)E + e];
        } else {
            const int* p = (const int*)ei;
            s = p[e]; d = p[E + e];
        }
    } else { s = e - E; d = e - E; }
    g_src[e] = s; g_dst[e] = d;
}

// ---------------- GEMM1: persistent, pre-split bf16, cp.async, fp16 out ------
// Block 128x128 tiles, 8 warps (2m x 4n), warp tile 64x32, k-tile 16, 3 stages.
__global__ void __launch_bounds__(256, 2) k_gemm1_mma(int M, int numTiles) {
    extern __shared__ __align__(16) uint8_t sm[];
    int tid = threadIdx.x, lane = tid & 31, wid = tid >> 5;
    int warp_m = wid & 1, warp_n = wid >> 1;
    uint32_t uS = smem_u32(sm);

    int cRow = tid >> 1, cHalf = tid & 1;
    uint32_t cDst = (uint32_t)(cRow * ROWS_B + cHalf * 16);

    // ldmatrix per-lane offsets (relative to region base)
    uint32_t aRel[4], bRel[2];
#pragma unroll
    for (int mt = 0; mt < 4; mt++)
        aRel[mt] = (uint32_t)((warp_m * 64 + mt * 16 + (lane & 15)) * ROWS_B
                              + (((lane >> 4) & 1) << 4));
    {
        int b_n = (lane & 7) | ((lane & 16) >> 1);
        int b_kb = (lane & 8) << 1;
#pragma unroll
        for (int bt = 0; bt < 2; bt++)
            bRel[bt] = (uint32_t)((warp_n * 32 + bt * 16 + b_n) * ROWS_B + b_kb);
    }

    for (int tile = blockIdx.x; tile < numTiles; tile += GRID_G1) {
        int rowBase = (tile >> 2) << 7;
        int colBase = (tile & 3) << 7;

        uint32_t aSz = (rowBase + cRow) < M ? 16u : 0u;
        const __nv_bfloat16* Ah = g_xh + (size_t)(rowBase + cRow) * NFEAT + cHalf * 8;
        const __nv_bfloat16* Al = g_xl + (size_t)(rowBase + cRow) * NFEAT + cHalf * 8;
        const __nv_bfloat16* Bh = g_wth + (size_t)(colBase + cRow) * NFEAT + cHalf * 8;
        const __nv_bfloat16* Bl = g_wtl + (size_t)(colBase + cRow) * NFEAT + cHalf * 8;

        float c[4][4][4];
#pragma unroll
        for (int i = 0; i < 4; i++)
#pragma unroll
            for (int j = 0; j < 4; j++)
#pragma unroll
                for (int q = 0; q < 4; q++) c[i][j][q] = 0.f;

        auto issue = [&](int kt, int buf) {
            uint32_t b = uS + (uint32_t)buf * STG_BYTES + cDst;
            CP16(b,          Ah + kt * 16, aSz);
            CP16(b + OFF_AL, Al + kt * 16, aSz);
            CP16(b + OFF_BH, Bh + kt * 16, 16u);
            CP16(b + OFF_BL, Bl + kt * 16, 16u);
        };

        __syncthreads();   // protect stage buffers from previous tile's readers
        issue(0, 0); CP_COMMIT();
        issue(1, 1); CP_COMMIT();

        const int NT = NFEAT / 16;   // 32
        for (int kt = 0; kt < NT; kt++) {
            CP_WAIT1();
            __syncthreads();
            uint32_t base = uS + (uint32_t)(kt % 3) * STG_BYTES;

            uint32_t ah[4][4], bh[2][4];
#pragma unroll
            for (int mt = 0; mt < 4; mt++) ldsm4(base + aRel[mt], ah[mt]);
#pragma unroll
            for (int bt = 0; bt < 2; bt++) ldsm4(base + OFF_BH + bRel[bt], bh[bt]);
#pragma unroll
            for (int mt = 0; mt < 4; mt++)
#pragma unroll
                for (int nt = 0; nt < 4; nt++) {
                    int bi = nt >> 1, bj = (nt & 1) << 1;
                    MMA_BF16(c[mt][nt], ah[mt], bh[bi][bj], bh[bi][bj + 1]);
                }
            uint32_t bl[2][4];
#pragma unroll
            for (int bt = 0; bt < 2; bt++) ldsm4(base + OFF_BL + bRel[bt], bl[bt]);
#pragma unroll
            for (int mt = 0; mt < 4; mt++)
#pragma unroll
                for (int nt = 0; nt < 4; nt++) {
                    int bi = nt >> 1, bj = (nt & 1) << 1;
                    MMA_BF16(c[mt][nt], ah[mt], bl[bi][bj], bl[bi][bj + 1]);
                }
            uint32_t al[4][4];
#pragma unroll
            for (int mt = 0; mt < 4; mt++) ldsm4(base + OFF_AL + aRel[mt], al[mt]);
#pragma unroll
            for (int mt = 0; mt < 4; mt++)
#pragma unroll
                for (int nt = 0; nt < 4; nt++) {
                    int bi = nt >> 1, bj = (nt & 1) << 1;
                    MMA_BF16(c[mt][nt], al[mt], bh[bi][bj], bh[bi][bj + 1]);
                }

            if (kt + 2 < NT) issue(kt + 2, (kt + 2) % 3);
            CP_COMMIT();
        }

        // epilogue: fp16 output
#pragma unroll
        for (int mt = 0; mt < 4; mt++) {
            int r0 = rowBase + warp_m * 64 + mt * 16 + (lane >> 2);
#pragma unroll
            for (int nt = 0; nt < 4; nt++) {
                int col = colBase + warp_n * 32 + nt * 8 + ((lane & 3) << 1);
                if (r0 < M)
                    *(__half2*)&g_h1h[(size_t)r0 * HHC + col] =
                        __floats2half2_rn(c[mt][nt][0], c[mt][nt][1]);
                if (r0 + 8 < M)
                    *(__half2*)&g_h1h[(size_t)(r0 + 8) * HHC + col] =
                        __floats2half2_rn(c[mt][nt][2], c[mt][nt][3]);
            }
        }
    }
}

// ---------------- CSR build ----------------
__global__ void k_init0(int M) {
    int i = blockIdx.x * blockDim.x + threadIdx.x;
    if (i < M) { g_deg[i] = 0; g_fill[i] = 0; }
}
__global__ void k_count(int EN) {
    int e = blockIdx.x * blockDim.x + threadIdx.x;
    if (e < EN) atomicAdd(&g_deg[g_dst[e]], 1);
}
__global__ void k_scan(int M) {
    __shared__ int ss[1024];
    int t = threadIdx.x;
    int CH = (M + 1023) >> 10;
    int base = t * CH;
    int sum = 0;
    for (int i = 0; i < CH; i++) { int idx = base + i; if (idx < M) sum += g_deg[idx]; }
    ss[t] = sum; __syncthreads();
    for (int off = 1; off < 1024; off <<= 1) {
        int v = (t >= off) ? ss[t - off] : 0;
        __syncthreads();
        ss[t] += v;
        __syncthreads();
    }
    int off = (t == 0) ? 0 : ss[t - 1];
    for (int i = 0; i < CH; i++) {
        int idx = base + i;
        if (idx < M) { g_row[idx] = off; off += g_deg[idx]; }
    }
    if (t == 1023) g_row[M] = ss[1023];
}
__global__ void k_scatter(int EN) {
    int e = blockIdx.x * blockDim.x + threadIdx.x;
    if (e >= EN) return;
    int d = g_dst[e];
    int p = g_row[d] + atomicAdd(&g_fill[d], 1);
    g_csrc[p] = g_src[e];
}

// ---------------- alpha1 (fp16 h1) ----------------
__global__ void k_alpha1(const float* __restrict__ asrc, const float* __restrict__ adst, int M) {
    int gw = (blockIdx.x * blockDim.x + threadIdx.x) >> 5;
    int lane = threadIdx.x & 31;
    if (gw >= M) return;
    const __half2* hr = (const __half2*)(g_h1h + (size_t)gw * HHC);
    const float2* as2p = (const float2*)asrc;
    const float2* ad2p = (const float2*)adst;
#pragma unroll
    for (int h = 0; h < NHEAD; h++) {
        float2 v = __half22float2(hr[h * 32 + lane]);
        float2 a = as2p[h * 32 + lane];
        float2 d = ad2p[h * 32 + lane];
        float sa = v.x * a.x + v.y * a.y;
        float sd = v.x * d.x + v.y * d.y;
#pragma unroll
        for (int o = 16; o; o >>= 1) {
            sa += __shfl_down_sync(0xffffffffu, sa, o);
            sd += __shfl_down_sync(0xffffffffu, sd, o);
        }
        if (lane == 0) { g_as1[gw * 8 + h] = sa; g_ad1[gw * 8 + h] = sd; }
    }
}

// ---------------- layer1 softmax ----------------
__global__ void k_soft1(int M) {
    int n = (blockIdx.x * blockDim.x + threadIdx.x) >> 5;
    int lane = threadIdx.x & 31;
    if (n >= M) return;
    int start = g_row[n], end = g_row[n + 1];
    int h = lane & 7, slot = lane >> 3;
    float ad = g_ad1[n * 8 + h];
    float mx = __int_as_float(0xff800000);
    for (int p = start + slot; p < end; p += 4) {
        float v = g_as1[g_csrc[p] * 8 + h] + ad;
        v = v >= 0.f ? v : NEG * v;
        mx = fmaxf(mx, v);
    }
    mx = fmaxf(mx, __shfl_xor_sync(0xffffffffu, mx, 8));
    mx = fmaxf(mx, __shfl_xor_sync(0xffffffffu, mx, 16));
    float den = 0.f;
    for (int p = start + slot; p < end; p += 4) {
        float v = g_as1[g_csrc[p] * 8 + h] + ad;
        v = v >= 0.f ? v : NEG * v;
        float ex = expf(v - mx);
        g_ex1[(size_t)p * 8 + h] = ex;
        den += ex;
    }
    den += __shfl_xor_sync(0xffffffffu, den, 8);
    den += __shfl_xor_sync(0xffffffffu, den, 16);
    if (slot == 0) g_inv1[n * 8 + h] = 1.f / den;
}

// ---------------- layer1 aggregation (fp16 gather) ----------------
__global__ void __launch_bounds__(128) k_aggr1(float* __restrict__ emb,
                                               const float* __restrict__ b1) {
    int n = blockIdx.x;
    int t = threadIdx.x;
    __shared__ float sinv[8];
    if (t < 8) sinv[t] = g_inv1[n * 8 + t];
    __syncthreads();
    int start = g_row[n], end = g_row[n + 1];
    int h = t >> 4;
    float inv = sinv[h];
    float4 acc = make_float4(0.f, 0.f, 0.f, 0.f);
    for (int p = start; p < end; p++) {
        int s = g_csrc[p];
        float a = g_ex1[(size_t)p * 8 + h] * inv;
        uint2 raw = *(const uint2*)(g_h1h + (size_t)s * HHC + (t << 2));
        float2 f01 = __half22float2(*(__half2*)&raw.x);
        float2 f23 = __half22float2(*(__half2*)&raw.y);
        acc.x += a * f01.x; acc.y += a * f01.y;
        acc.z += a * f23.x; acc.w += a * f23.y;
    }
    float4 bv = ((const float4*)b1)[t];
    acc.x += bv.x; acc.y += bv.y; acc.z += bv.z; acc.w += bv.w;
    ((float4*)(emb + (size_t)n * HHC))[t] = acc;
    float4 e;
    e.x = acc.x > 0.f ? acc.x : expm1f(acc.x);
    e.y = acc.y > 0.f ? acc.y : expm1f(acc.y);
    e.z = acc.z > 0.f ? acc.z : expm1f(acc.z);
    e.w = acc.w > 0.f ? acc.w : expm1f(acc.w);
    ((float4*)(g_hact + (size_t)n * HHC))[t] = e;
}

// ---------------- GEMM2 + alpha2 (fused) ----------------
__global__ void k_gemm2(const float* __restrict__ W2, const float* __restrict__ asrc,
                        const float* __restrict__ adst, int M) {
    __shared__ float Ws[NFEAT * NCLS];
    for (int i = threadIdx.x; i < NFEAT * NCLS; i += 256) Ws[i] = W2[i];
    __syncthreads();
    int c = threadIdx.x & 15;
    int n = blockIdx.x * 16 + (threadIdx.x >> 4);
    if (n >= M) return;
    const float4* hr4 = (const float4*)(g_hact + (size_t)n * HHC);
    float acc = 0.f;
#pragma unroll 8
    for (int k4 = 0; k4 < NFEAT / 4; k4++) {
        float4 hv = hr4[k4];
        int k = k4 * 4;
        acc += hv.x * Ws[(k + 0) * NCLS + c];
        acc += hv.y * Ws[(k + 1) * NCLS + c];
        acc += hv.z * Ws[(k + 2) * NCLS + c];
        acc += hv.w * Ws[(k + 3) * NCLS + c];
    }
    g_h2[(size_t)n * NCLS + c] = acc;
    float sa = acc * asrc[c], sd = acc * adst[c];
#pragma unroll
    for (int o = 8; o; o >>= 1) {
        sa += __shfl_xor_sync(0xffffffffu, sa, o);
        sd += __shfl_xor_sync(0xffffffffu, sd, o);
    }
    if (c == 0) { g_as2[n] = sa; g_ad2[n] = sd; }
}

// ---------------- layer2 softmax ----------------
__global__ void k_soft2(int M) {
    int n = (blockIdx.x * blockDim.x + threadIdx.x) >> 5;
    int lane = threadIdx.x & 31;
    if (n >= M) return;
    int start = g_row[n], end = g_row[n + 1];
    float ad = g_ad2[n];
    float mx = __int_as_float(0xff800000);
    for (int p = start + lane; p < end; p += 32) {
        float v = g_as2[g_csrc[p]] + ad;
        v = v >= 0.f ? v : NEG * v;
        mx = fmaxf(mx, v);
    }
#pragma unroll
    for (int o = 16; o; o >>= 1) mx = fmaxf(mx, __shfl_xor_sync(0xffffffffu, mx, o));
    float den = 0.f;
    for (int p = start + lane; p < end; p += 32) {
        float v = g_as2[g_csrc[p]] + ad;
        v = v >= 0.f ? v : NEG * v;
        float ex = expf(v - mx);
        g_ex2[p] = ex;
        den += ex;
    }
#pragma unroll
    for (int o = 16; o; o >>= 1) den += __shfl_xor_sync(0xffffffffu, den, o);
    if (lane == 0) g_inv2[n] = 1.f / den;
}

// ---------------- layer2 aggregation ----------------
__global__ void k_aggr2(float* __restrict__ logits, const float* __restrict__ b2, int M) {
    int n = blockIdx.x * 8 + (threadIdx.x >> 4);
    int c = threadIdx.x & 15;
    if (n >= M) return;
    int start = g_row[n], end = g_row[n + 1];
    float inv = g_inv2[n];
    float acc = 0.f;
    for (int p = start; p < end; p++) {
        float a = g_ex2[p] * inv;
        acc += a * g_h2[(size_t)g_csrc[p] * NCLS + c];
    }
    logits[(size_t)n * NCLS + c] = acc + b2[c];
}

// ---------------- launch ----------------
extern "C" void kernel_launch(void* const* d_in, const int* in_sizes, int n_in,
                              void* d_out, int out_size) {
    const float* x     = (const float*)d_in[0];
    const void*  ei    = d_in[1];
    const float* w1    = (const float*)d_in[2];
    const float* asrc1 = (const float*)d_in[3];
    const float* adst1 = (const float*)d_in[4];
    const float* b1    = (const float*)d_in[5];
    const float* w2    = (const float*)d_in[6];
    const float* asrc2 = (const float*)d_in[7];
    const float* adst2 = (const float*)d_in[8];
    const float* b2    = (const float*)d_in[9];

    const int M  = in_sizes[0] / NFEAT;     // 50000
    const int E  = in_sizes[1] / 2;         // 800000
    const int EN = E + M;                   // 850000
    const int numTiles = ((M + 127) / 128) * 4;

    float* logits = (float*)d_out;
    float* emb    = logits + (size_t)M * NCLS;

    cudaFuncSetAttribute(k_gemm1_mma, cudaFuncAttributeMaxDynamicSharedMemorySize, DSMEM_G1);

    size_t n4 = (size_t)M * NFEAT / 4;
    k_split_x<<<(unsigned)((n4 + 255) / 256), 256>>>(x, n4);          // 0
    {
        dim3 g(16, 16), b(32, 8);
        k_split_wt<<<g, b>>>(w1);                                      // 1
    }
    k_detect<<<1, 256>>>((const unsigned int*)ei);                     // 2
    k_gemm1_mma<<<GRID_G1, 256, DSMEM_G1>>>(M, numTiles);              // 3 (profiled)

    k_convert<<<(EN + 255) / 256, 256>>>(ei, E, EN);
    k_init0<<<(M + 255) / 256, 256>>>(M);
    k_count<<<(EN + 255) / 256, 256>>>(EN);
    k_scan<<<1, 1024>>>(M);
    k_scatter<<<(EN + 255) / 256, 256>>>(EN);

    k_alpha1<<<((M * 32) + 255) / 256, 256>>>(asrc1, adst1, M);
    k_soft1<<<((M * 32) + 255) / 256, 256>>>(M);
    k_aggr1<<<M, 128>>>(emb, b1);

    k_gemm2<<<(M + 15) / 16, 256>>>(w2, asrc2, adst2, M);
    k_soft2<<<((M * 32) + 255) / 256, 256>>>(M);
    k_aggr2<<<(M + 7) / 8, 128>>>(logits, b2, M);
}

// round 10
// speedup vs baseline: 4.0727x; 1.1006x over previous
#include <cuda_runtime.h>
#include <cuda_bf16.h>
#include <cuda_fp16.h>
#include <math.h>
#include <stdint.h>

#define NNODES 50000
#define NFEAT  512
#define HHC    512
#define NHEAD  8
#define NCLS   16
#define NEG    0.2f
#define MAXEN  850000

// GEMM1 smem staging: 4 regions (Ah, Al, Bh, Bl) x 128 rows x 48B pitch
#define ROWS_B    48
#define REGION    (128 * ROWS_B)     // 6144
#define OFF_AL    REGION
#define OFF_BH    (2 * REGION)
#define OFF_BL    (3 * REGION)
#define STG_BYTES (4 * REGION)       // 24576 per stage
#define NSTAGE    4
#define DSMEM_G1  (NSTAGE * STG_BYTES)  // 98304

// ---------------- scratch ----------------
__device__ __half g_h1h  [(size_t)NNODES * HHC];  // layer1 features, fp16
__device__ __half g_hactH[(size_t)NNODES * HHC];  // elu(emb), fp16
__device__ float g_h2  [(size_t)NNODES * NCLS];
__device__ __nv_bfloat16 g_xh[(size_t)NNODES * NFEAT];
__device__ __nv_bfloat16 g_xl[(size_t)NNODES * NFEAT];
__device__ __nv_bfloat16 g_wth[NFEAT * HHC];   // W1^T hi: [n][k]
__device__ __nv_bfloat16 g_wtl[NFEAT * HHC];   // W1^T lo
__device__ float g_as1[NNODES * NHEAD];
__device__ float g_ad1[NNODES * NHEAD];
__device__ float g_inv1[NNODES * NHEAD];
__device__ float g_as2[NNODES];
__device__ float g_ad2[NNODES];
__device__ float g_inv2[NNODES];
__device__ float g_ex1[(size_t)MAXEN * NHEAD];
__device__ float g_ex2[MAXEN];
__device__ int   g_src[MAXEN];
__device__ int   g_dst[MAXEN];
__device__ int   g_csrc[MAXEN];
__device__ int   g_row[NNODES + 1];
__device__ int   g_deg[NNODES];
__device__ int   g_fill[NNODES];
__device__ int   g_is64;

// ---------------- helpers ----------------
__device__ __forceinline__ uint32_t smem_u32(const void* p) {
    uint32_t a;
    asm("{ .reg .u64 t; cvta.to.shared.u64 t, %1; cvt.u32.u64 %0, t; }" : "=r"(a) : "l"(p));
    return a;
}
__device__ __forceinline__ void ldsm4(uint32_t addr, uint32_t* r) {
    asm volatile("ldmatrix.sync.aligned.m8n8.x4.shared.b16 {%0,%1,%2,%3}, [%4];"
                 : "=r"(r[0]), "=r"(r[1]), "=r"(r[2]), "=r"(r[3]) : "r"(addr));
}
#define MMA_BF16(c, a, b0, b1) \
    asm volatile("mma.sync.aligned.m16n8k16.row.col.f32.bf16.bf16.f32 " \
        "{%0,%1,%2,%3}, {%4,%5,%6,%7}, {%8,%9}, {%0,%1,%2,%3};" \
        : "+f"((c)[0]), "+f"((c)[1]), "+f"((c)[2]), "+f"((c)[3]) \
        : "r"((a)[0]), "r"((a)[1]), "r"((a)[2]), "r"((a)[3]), "r"(b0), "r"(b1))

#define CP16(dst, src, sz) \
    asm volatile("cp.async.cg.shared.global [%0], [%1], 16, %2;" \
                 :: "r"(dst), "l"(src), "r"(sz) : "memory")
#define CP_COMMIT() asm volatile("cp.async.commit_group;" ::: "memory")
#define CP_WAIT2()  asm volatile("cp.async.wait_group 2;" ::: "memory")

__device__ __forceinline__ void splitf(float a, __nv_bfloat16& h, __nv_bfloat16& l) {
    h = __float2bfloat16_rn(a);
    l = __float2bfloat16_rn(a - __bfloat162float(h));
}

// ---------------- split x -> bf16 hi/lo ----------------
__global__ void k_split_x(const float* __restrict__ x, size_t n4) {
    size_t i = (size_t)blockIdx.x * blockDim.x + threadIdx.x;
    if (i >= n4) return;
    float4 v = ((const float4*)x)[i];
    __nv_bfloat16 h0, h1, h2, h3, l0, l1, l2, l3;
    splitf(v.x, h0, l0); splitf(v.y, h1, l1);
    splitf(v.z, h2, l2); splitf(v.w, h3, l3);
    ushort4 H = make_ushort4(__bfloat16_as_ushort(h0), __bfloat16_as_ushort(h1),
                             __bfloat16_as_ushort(h2), __bfloat16_as_ushort(h3));
    ushort4 L = make_ushort4(__bfloat16_as_ushort(l0), __bfloat16_as_ushort(l1),
                             __bfloat16_as_ushort(l2), __bfloat16_as_ushort(l3));
    ((ushort4*)g_xh)[i] = H;
    ((ushort4*)g_xl)[i] = L;
}

// ---------------- W1 transpose + split ----------------
__global__ void k_split_wt(const float* __restrict__ w1) {
    __shared__ float t[32][33];
    int bx = blockIdx.x * 32, by = blockIdx.y * 32;
#pragma unroll
    for (int j = 0; j < 32; j += 8)
        t[threadIdx.y + j][threadIdx.x] = w1[(size_t)(by + threadIdx.y + j) * HHC + bx + threadIdx.x];
    __syncthreads();
#pragma unroll
    for (int j = 0; j < 32; j += 8) {
        float v = t[threadIdx.x][threadIdx.y + j];
        __nv_bfloat16 h, l;
        splitf(v, h, l);
        size_t o = (size_t)(bx + threadIdx.y + j) * NFEAT + by + threadIdx.x;
        g_wth[o] = h;
        g_wtl[o] = l;
    }
}

// ---------------- edge dtype sniff ----------------
__global__ void k_detect(const unsigned int* __restrict__ ei32) {
    __shared__ int nz;
    if (threadIdx.x == 0) nz = 0;
    __syncthreads();
    for (int i = threadIdx.x; i < 4096; i += blockDim.x)
        if (ei32[2 * i + 1] != 0u) atomicOr(&nz, 1);
    __syncthreads();
    if (threadIdx.x == 0) g_is64 = nz ? 0 : 1;
}

// ---------------- GEMM1: pre-split bf16, cp.async 4-stage, fp16 out ----------
// Block 128x128, 8 warps (2m x 4n), warp tile 64x32, k-tile 16.
__global__ void __launch_bounds__(256, 2) k_gemm1_mma(int M) {
    extern __shared__ __align__(16) uint8_t sm[];
    int tid = threadIdx.x, lane = tid & 31, wid = tid >> 5;
    int warp_m = wid & 1, warp_n = wid >> 1;
    int rowBase = blockIdx.y << 7, colBase = blockIdx.x << 7;
    uint32_t uS = smem_u32(sm);

    int cRow = tid >> 1, cHalf = tid & 1;
    uint32_t aSz = (rowBase + cRow) < M ? 16u : 0u;
    const __nv_bfloat16* Ah = g_xh + (size_t)(rowBase + cRow) * NFEAT + cHalf * 8;
    const __nv_bfloat16* Al = g_xl + (size_t)(rowBase + cRow) * NFEAT + cHalf * 8;
    const __nv_bfloat16* Bh = g_wth + (size_t)(colBase + cRow) * NFEAT + cHalf * 8;
    const __nv_bfloat16* Bl = g_wtl + (size_t)(colBase + cRow) * NFEAT + cHalf * 8;
    uint32_t cDst = (uint32_t)(cRow * ROWS_B + cHalf * 16);

    uint32_t aRel[4], bRel[2];
#pragma unroll
    for (int mt = 0; mt < 4; mt++)
        aRel[mt] = (uint32_t)((warp_m * 64 + mt * 16 + (lane & 15)) * ROWS_B
                              + (((lane >> 4) & 1) << 4));
    {
        int b_n = (lane & 7) | ((lane & 16) >> 1);
        int b_kb = (lane & 8) << 1;
#pragma unroll
        for (int bt = 0; bt < 2; bt++)
            bRel[bt] = (uint32_t)((warp_n * 32 + bt * 16 + b_n) * ROWS_B + b_kb);
    }

    float c[4][4][4];
#pragma unroll
    for (int i = 0; i < 4; i++)
#pragma unroll
        for (int j = 0; j < 4; j++)
#pragma unroll
            for (int q = 0; q < 4; q++) c[i][j][q] = 0.f;

    auto issue = [&](int kt, int buf) {
        uint32_t b = uS + (uint32_t)buf * STG_BYTES + cDst;
        CP16(b,          Ah + kt * 16, aSz);
        CP16(b + OFF_AL, Al + kt * 16, aSz);
        CP16(b + OFF_BH, Bh + kt * 16, 16u);
        CP16(b + OFF_BL, Bl + kt * 16, 16u);
    };

    issue(0, 0); CP_COMMIT();
    issue(1, 1); CP_COMMIT();
    issue(2, 2); CP_COMMIT();

    const int NT = NFEAT / 16;   // 32
    for (int kt = 0; kt < NT; kt++) {
        CP_WAIT2();
        __syncthreads();
        uint32_t base = uS + (uint32_t)(kt % NSTAGE) * STG_BYTES;

        uint32_t ah[4][4], bh[2][4];
#pragma unroll
        for (int mt = 0; mt < 4; mt++) ldsm4(base + aRel[mt], ah[mt]);
#pragma unroll
        for (int bt = 0; bt < 2; bt++) ldsm4(base + OFF_BH + bRel[bt], bh[bt]);
#pragma unroll
        for (int mt = 0; mt < 4; mt++)
#pragma unroll
            for (int nt = 0; nt < 4; nt++) {
                int bi = nt >> 1, bj = (nt & 1) << 1;
                MMA_BF16(c[mt][nt], ah[mt], bh[bi][bj], bh[bi][bj + 1]);
            }
        uint32_t bl[2][4];
#pragma unroll
        for (int bt = 0; bt < 2; bt++) ldsm4(base + OFF_BL + bRel[bt], bl[bt]);
#pragma unroll
        for (int mt = 0; mt < 4; mt++)
#pragma unroll
            for (int nt = 0; nt < 4; nt++) {
                int bi = nt >> 1, bj = (nt & 1) << 1;
                MMA_BF16(c[mt][nt], ah[mt], bl[bi][bj], bl[bi][bj + 1]);
            }
        uint32_t al[4][4];
#pragma unroll
        for (int mt = 0; mt < 4; mt++) ldsm4(base + OFF_AL + aRel[mt], al[mt]);
#pragma unroll
        for (int mt = 0; mt < 4; mt++)
#pragma unroll
            for (int nt = 0; nt < 4; nt++) {
                int bi = nt >> 1, bj = (nt & 1) << 1;
                MMA_BF16(c[mt][nt], al[mt], bh[bi][bj], bh[bi][bj + 1]);
            }

        if (kt + 3 < NT) issue(kt + 3, (kt + 3) % NSTAGE);
        CP_COMMIT();
    }

    // epilogue: fp16 output
#pragma unroll
    for (int mt = 0; mt < 4; mt++) {
        int r0 = rowBase + warp_m * 64 + mt * 16 + (lane >> 2);
#pragma unroll
        for (int nt = 0; nt < 4; nt++) {
            int col = colBase + warp_n * 32 + nt * 8 + ((lane & 3) << 1);
            if (r0 < M)
                *(__half2*)&g_h1h[(size_t)r0 * HHC + col] =
                    __floats2half2_rn(c[mt][nt][0], c[mt][nt][1]);
            if (r0 + 8 < M)
                *(__half2*)&g_h1h[(size_t)(r0 + 8) * HHC + col] =
                    __floats2half2_rn(c[mt][nt][2], c[mt][nt][3]);
        }
    }
}

// ---------------- CSR build ----------------
__global__ void k_init0(int M) {
    int i = blockIdx.x * blockDim.x + threadIdx.x;
    if (i < M) { g_deg[i] = 0; g_fill[i] = 0; }
}
// fused: edge canonicalization + degree count
__global__ void k_convcount(const void* __restrict__ ei, int E, int EN) {
    int e = blockIdx.x * blockDim.x + threadIdx.x;
    if (e >= EN) return;
    int s, d;
    if (e < E) {
        if (g_is64) {
            const long long* p = (const long long*)ei;
            s = (int)p[e]; d = (int)p[(size_t)E + e];
        } else {
            const int* p = (const int*)ei;
            s = p[e]; d = p[E + e];
        }
    } else { s = e - E; d = e - E; }
    g_src[e] = s; g_dst[e] = d;
    atomicAdd(&g_deg[d], 1);
}
__global__ void k_scan(int M) {
    __shared__ int ss[1024];
    int t = threadIdx.x;
    int CH = (M + 1023) >> 10;
    int base = t * CH;
    int sum = 0;
    for (int i = 0; i < CH; i++) { int idx = base + i; if (idx < M) sum += g_deg[idx]; }
    ss[t] = sum; __syncthreads();
    for (int off = 1; off < 1024; off <<= 1) {
        int v = (t >= off) ? ss[t - off] : 0;
        __syncthreads();
        ss[t] += v;
        __syncthreads();
    }
    int off = (t == 0) ? 0 : ss[t - 1];
    for (int i = 0; i < CH; i++) {
        int idx = base + i;
        if (idx < M) { g_row[idx] = off; off += g_deg[idx]; }
    }
    if (t == 1023) g_row[M] = ss[1023];
}
__global__ void k_scatter(int EN) {
    int e = blockIdx.x * blockDim.x + threadIdx.x;
    if (e >= EN) return;
    int d = g_dst[e];
    int p = g_row[d] + atomicAdd(&g_fill[d], 1);
    g_csrc[p] = g_src[e];
}

// ---------------- alpha1 (fp16 h1) ----------------
__global__ void k_alpha1(const float* __restrict__ asrc, const float* __restrict__ adst, int M) {
    int gw = (blockIdx.x * blockDim.x + threadIdx.x) >> 5;
    int lane = threadIdx.x & 31;
    if (gw >= M) return;
    const __half2* hr = (const __half2*)(g_h1h + (size_t)gw * HHC);
    const float2* as2p = (const float2*)asrc;
    const float2* ad2p = (const float2*)adst;
#pragma unroll
    for (int h = 0; h < NHEAD; h++) {
        float2 v = __half22float2(hr[h * 32 + lane]);
        float2 a = as2p[h * 32 + lane];
        float2 d = ad2p[h * 32 + lane];
        float sa = v.x * a.x + v.y * a.y;
        float sd = v.x * d.x + v.y * d.y;
#pragma unroll
        for (int o = 16; o; o >>= 1) {
            sa += __shfl_down_sync(0xffffffffu, sa, o);
            sd += __shfl_down_sync(0xffffffffu, sd, o);
        }
        if (lane == 0) { g_as1[gw * 8 + h] = sa; g_ad1[gw * 8 + h] = sd; }
    }
}

// ---------------- layer1 softmax ----------------
__global__ void k_soft1(int M) {
    int n = (blockIdx.x * blockDim.x + threadIdx.x) >> 5;
    int lane = threadIdx.x & 31;
    if (n >= M) return;
    int start = g_row[n], end = g_row[n + 1];
    int h = lane & 7, slot = lane >> 3;
    float ad = g_ad1[n * 8 + h];
    float mx = __int_as_float(0xff800000);
    for (int p = start + slot; p < end; p += 4) {
        float v = g_as1[g_csrc[p] * 8 + h] + ad;
        v = v >= 0.f ? v : NEG * v;
        mx = fmaxf(mx, v);
    }
    mx = fmaxf(mx, __shfl_xor_sync(0xffffffffu, mx, 8));
    mx = fmaxf(mx, __shfl_xor_sync(0xffffffffu, mx, 16));
    float den = 0.f;
    for (int p = start + slot; p < end; p += 4) {
        float v = g_as1[g_csrc[p] * 8 + h] + ad;
        v = v >= 0.f ? v : NEG * v;
        float ex = expf(v - mx);
        g_ex1[(size_t)p * 8 + h] = ex;
        den += ex;
    }
    den += __shfl_xor_sync(0xffffffffu, den, 8);
    den += __shfl_xor_sync(0xffffffffu, den, 16);
    if (slot == 0) g_inv1[n * 8 + h] = 1.f / den;
}

// ---------------- layer1 aggregation (fp16 gather, fp16 hact out) ------------
__global__ void __launch_bounds__(128) k_aggr1(float* __restrict__ emb,
                                               const float* __restrict__ b1) {
    int n = blockIdx.x;
    int t = threadIdx.x;
    __shared__ float sinv[8];
    if (t < 8) sinv[t] = g_inv1[n * 8 + t];
    __syncthreads();
    int start = g_row[n], end = g_row[n + 1];
    int h = t >> 4;
    float inv = sinv[h];
    float4 acc = make_float4(0.f, 0.f, 0.f, 0.f);
    for (int p = start; p < end; p++) {
        int s = g_csrc[p];
        float a = g_ex1[(size_t)p * 8 + h] * inv;
        uint2 raw = *(const uint2*)(g_h1h + (size_t)s * HHC + (t << 2));
        float2 f01 = __half22float2(*(__half2*)&raw.x);
        float2 f23 = __half22float2(*(__half2*)&raw.y);
        acc.x += a * f01.x; acc.y += a * f01.y;
        acc.z += a * f23.x; acc.w += a * f23.y;
    }
    float4 bv = ((const float4*)b1)[t];
    acc.x += bv.x; acc.y += bv.y; acc.z += bv.z; acc.w += bv.w;
    ((float4*)(emb + (size_t)n * HHC))[t] = acc;
    float ex = acc.x > 0.f ? acc.x : expm1f(acc.x);
    float ey = acc.y > 0.f ? acc.y : expm1f(acc.y);
    float ez = acc.z > 0.f ? acc.z : expm1f(acc.z);
    float ew = acc.w > 0.f ? acc.w : expm1f(acc.w);
    uint2 out;
    *(__half2*)&out.x = __floats2half2_rn(ex, ey);
    *(__half2*)&out.y = __floats2half2_rn(ez, ew);
    *(uint2*)(g_hactH + (size_t)n * HHC + (t << 2)) = out;
}

// ---------------- GEMM2 + alpha2 (fused, fp16 hact) ----------------
__global__ void k_gemm2(const float* __restrict__ W2, const float* __restrict__ asrc,
                        const float* __restrict__ adst, int M) {
    __shared__ float Ws[NFEAT * NCLS];
    for (int i = threadIdx.x; i < NFEAT * NCLS; i += 256) Ws[i] = W2[i];
    __syncthreads();
    int c = threadIdx.x & 15;
    int n = blockIdx.x * 16 + (threadIdx.x >> 4);
    if (n >= M) return;
    const uint4* hr8 = (const uint4*)(g_hactH + (size_t)n * HHC);
    float acc = 0.f;
#pragma unroll 4
    for (int k8 = 0; k8 < NFEAT / 8; k8++) {
        uint4 raw = hr8[k8];
        float2 f0 = __half22float2(*(__half2*)&raw.x);
        float2 f1 = __half22float2(*(__half2*)&raw.y);
        float2 f2 = __half22float2(*(__half2*)&raw.z);
        float2 f3 = __half22float2(*(__half2*)&raw.w);
        int k = k8 * 8;
        acc += f0.x * Ws[(k + 0) * NCLS + c] + f0.y * Ws[(k + 1) * NCLS + c];
        acc += f1.x * Ws[(k + 2) * NCLS + c] + f1.y * Ws[(k + 3) * NCLS + c];
        acc += f2.x * Ws[(k + 4) * NCLS + c] + f2.y * Ws[(k + 5) * NCLS + c];
        acc += f3.x * Ws[(k + 6) * NCLS + c] + f3.y * Ws[(k + 7) * NCLS + c];
    }
    g_h2[(size_t)n * NCLS + c] = acc;
    float sa = acc * asrc[c], sd = acc * adst[c];
#pragma unroll
    for (int o = 8; o; o >>= 1) {
        sa += __shfl_xor_sync(0xffffffffu, sa, o);
        sd += __shfl_xor_sync(0xffffffffu, sd, o);
    }
    if (c == 0) { g_as2[n] = sa; g_ad2[n] = sd; }
}

// ---------------- layer2 softmax ----------------
__global__ void k_soft2(int M) {
    int n = (blockIdx.x * blockDim.x + threadIdx.x) >> 5;
    int lane = threadIdx.x & 31;
    if (n >= M) return;
    int start = g_row[n], end = g_row[n + 1];
    float ad = g_ad2[n];
    float mx = __int_as_float(0xff800000);
    for (int p = start + lane; p < end; p += 32) {
        float v = g_as2[g_csrc[p]] + ad;
        v = v >= 0.f ? v : NEG * v;
        mx = fmaxf(mx, v);
    }
#pragma unroll
    for (int o = 16; o; o >>= 1) mx = fmaxf(mx, __shfl_xor_sync(0xffffffffu, mx, o));
    float den = 0.f;
    for (int p = start + lane; p < end; p += 32) {
        float v = g_as2[g_csrc[p]] + ad;
        v = v >= 0.f ? v : NEG * v;
        float ex = expf(v - mx);
        g_ex2[p] = ex;
        den += ex;
    }
#pragma unroll
    for (int o = 16; o; o >>= 1) den += __shfl_xor_sync(0xffffffffu, den, o);
    if (lane == 0) g_inv2[n] = 1.f / den;
}

// ---------------- layer2 aggregation ----------------
__global__ void k_aggr2(float* __restrict__ logits, const float* __restrict__ b2, int M) {
    int n = blockIdx.x * 8 + (threadIdx.x >> 4);
    int c = threadIdx.x & 15;
    if (n >= M) return;
    int start = g_row[n], end = g_row[n + 1];
    float inv = g_inv2[n];
    float acc = 0.f;
    for (int p = start; p < end; p++) {
        float a = g_ex2[p] * inv;
        acc += a * g_h2[(size_t)g_csrc[p] * NCLS + c];
    }
    logits[(size_t)n * NCLS + c] = acc + b2[c];
}

// ---------------- launch ----------------
extern "C" void kernel_launch(void* const* d_in, const int* in_sizes, int n_in,
                              void* d_out, int out_size) {
    const float* x     = (const float*)d_in[0];
    const void*  ei    = d_in[1];
    const float* w1    = (const float*)d_in[2];
    const float* asrc1 = (const float*)d_in[3];
    const float* adst1 = (const float*)d_in[4];
    const float* b1    = (const float*)d_in[5];
    const float* w2    = (const float*)d_in[6];
    const float* asrc2 = (const float*)d_in[7];
    const float* adst2 = (const float*)d_in[8];
    const float* b2    = (const float*)d_in[9];

    const int M  = in_sizes[0] / NFEAT;     // 50000
    const int E  = in_sizes[1] / 2;         // 800000
    const int EN = E + M;                   // 850000

    float* logits = (float*)d_out;
    float* emb    = logits + (size_t)M * NCLS;

    cudaFuncSetAttribute(k_gemm1_mma, cudaFuncAttributeMaxDynamicSharedMemorySize, DSMEM_G1);

    size_t n4 = (size_t)M * NFEAT / 4;
    k_split_x<<<(unsigned)((n4 + 255) / 256), 256>>>(x, n4);          // 0
    {
        dim3 g(16, 16), b(32, 8);
        k_split_wt<<<g, b>>>(w1);                                      // 1
    }
    k_detect<<<1, 256>>>((const unsigned int*)ei);                     // 2
    {
        dim3 grid(HHC / 128, (M + 127) / 128);
        k_gemm1_mma<<<grid, 256, DSMEM_G1>>>(M);                       // 3 (profiled)
    }
    k_init0<<<(M + 255) / 256, 256>>>(M);
    k_convcount<<<(EN + 255) / 256, 256>>>(ei, E, EN);
    k_scan<<<1, 1024>>>(M);
    k_scatter<<<(EN + 255) / 256, 256>>>(EN);

    k_alpha1<<<((M * 32) + 255) / 256, 256>>>(asrc1, adst1, M);
    k_soft1<<<((M * 32) + 255) / 256, 256>>>(M);
    k_aggr1<<<M, 128>>>(emb, b1);

    k_gemm2<<<(M + 15) / 16, 256>>>(w2, asrc2, adst2, M);
    k_soft2<<<((M * 32) + 255) / 256, 256>>>(M);
    k_aggr2<<<(M + 7) / 8, 128>>>(logits, b2, M);
}

// round 11
// speedup vs baseline: 4.2604x; 1.0461x over previous
#include <cuda_runtime.h>
#include <cuda_bf16.h>
#include <cuda_fp16.h>
#include <math.h>
#include <stdint.h>

#define NNODES 50000
#define NFEAT  512
#define HHC    512
#define NHEAD  8
#define NCLS   16
#define NEG    0.2f
#define MAXEN  850000

// GEMM1 smem staging: 4 regions (Ah, Al, Bh, Bl) x 128 rows x 48B pitch
#define ROWS_B    48
#define REGION    (128 * ROWS_B)     // 6144
#define OFF_AL    REGION
#define OFF_BH    (2 * REGION)
#define OFF_BL    (3 * REGION)
#define STG_BYTES (4 * REGION)       // 24576 per stage
#define NSTAGE    4
#define DSMEM_G1  (NSTAGE * STG_BYTES)  // 98304

// ---------------- scratch ----------------
__device__ __half g_h1h  [(size_t)NNODES * HHC];  // layer1 features, fp16
__device__ __half g_hactH[(size_t)NNODES * HHC];  // elu(emb), fp16
__device__ float g_h2  [(size_t)NNODES * NCLS];
__device__ __nv_bfloat16 g_xh[(size_t)NNODES * NFEAT];
__device__ __nv_bfloat16 g_xl[(size_t)NNODES * NFEAT];
__device__ __nv_bfloat16 g_wth[NFEAT * HHC];   // W1^T hi: [n][k]
__device__ __nv_bfloat16 g_wtl[NFEAT * HHC];   // W1^T lo
__device__ float g_as1[NNODES * NHEAD];
__device__ float g_ad1[NNODES * NHEAD];
__device__ float g_inv1[NNODES * NHEAD];
__device__ float g_as2[NNODES];
__device__ float g_ad2[NNODES];
__device__ float g_inv2[NNODES];
__device__ float g_ex1[(size_t)MAXEN * NHEAD];
__device__ float g_ex2[MAXEN];
__device__ int   g_src[MAXEN];
__device__ int   g_dst[MAXEN];
__device__ int   g_csrc[MAXEN];
__device__ int   g_row[NNODES + 1];
__device__ int   g_deg[NNODES];
__device__ int   g_fill[NNODES];
__device__ int   g_is64;

// ---------------- helpers ----------------
__device__ __forceinline__ uint32_t smem_u32(const void* p) {
    uint32_t a;
    asm("{ .reg .u64 t; cvta.to.shared.u64 t, %1; cvt.u32.u64 %0, t; }" : "=r"(a) : "l"(p));
    return a;
}
__device__ __forceinline__ void ldsm4(uint32_t addr, uint32_t* r) {
    asm volatile("ldmatrix.sync.aligned.m8n8.x4.shared.b16 {%0,%1,%2,%3}, [%4];"
                 : "=r"(r[0]), "=r"(r[1]), "=r"(r[2]), "=r"(r[3]) : "r"(addr));
}
#define MMA_BF16(c, a, b0, b1) \
    asm volatile("mma.sync.aligned.m16n8k16.row.col.f32.bf16.bf16.f32 " \
        "{%0,%1,%2,%3}, {%4,%5,%6,%7}, {%8,%9}, {%0,%1,%2,%3};" \
        : "+f"((c)[0]), "+f"((c)[1]), "+f"((c)[2]), "+f"((c)[3]) \
        : "r"((a)[0]), "r"((a)[1]), "r"((a)[2]), "r"((a)[3]), "r"(b0), "r"(b1))

#define CP16(dst, src, sz) \
    asm volatile("cp.async.cg.shared.global [%0], [%1], 16, %2;" \
                 :: "r"(dst), "l"(src), "r"(sz) : "memory")
#define CP_COMMIT() asm volatile("cp.async.commit_group;" ::: "memory")
#define CP_WAIT2()  asm volatile("cp.async.wait_group 2;" ::: "memory")

__device__ __forceinline__ void splitf(float a, __nv_bfloat16& h, __nv_bfloat16& l) {
    h = __float2bfloat16_rn(a);
    l = __float2bfloat16_rn(a - __bfloat162float(h));
}

// ---------------- split x -> bf16 hi/lo ----------------
__global__ void k_split_x(const float* __restrict__ x, size_t n4) {
    size_t i = (size_t)blockIdx.x * blockDim.x + threadIdx.x;
    if (i >= n4) return;
    float4 v = ((const float4*)x)[i];
    __nv_bfloat16 h0, h1, h2, h3, l0, l1, l2, l3;
    splitf(v.x, h0, l0); splitf(v.y, h1, l1);
    splitf(v.z, h2, l2); splitf(v.w, h3, l3);
    ushort4 H = make_ushort4(__bfloat16_as_ushort(h0), __bfloat16_as_ushort(h1),
                             __bfloat16_as_ushort(h2), __bfloat16_as_ushort(h3));
    ushort4 L = make_ushort4(__bfloat16_as_ushort(l0), __bfloat16_as_ushort(l1),
                             __bfloat16_as_ushort(l2), __bfloat16_as_ushort(l3));
    ((ushort4*)g_xh)[i] = H;
    ((ushort4*)g_xl)[i] = L;
}

// ---------------- W1 transpose + split ----------------
__global__ void k_split_wt(const float* __restrict__ w1) {
    __shared__ float t[32][33];
    int bx = blockIdx.x * 32, by = blockIdx.y * 32;
#pragma unroll
    for (int j = 0; j < 32; j += 8)
        t[threadIdx.y + j][threadIdx.x] = w1[(size_t)(by + threadIdx.y + j) * HHC + bx + threadIdx.x];
    __syncthreads();
#pragma unroll
    for (int j = 0; j < 32; j += 8) {
        float v = t[threadIdx.x][threadIdx.y + j];
        __nv_bfloat16 h, l;
        splitf(v, h, l);
        size_t o = (size_t)(bx + threadIdx.y + j) * NFEAT + by + threadIdx.x;
        g_wth[o] = h;
        g_wtl[o] = l;
    }
}

// ---------------- edge dtype sniff ----------------
__global__ void k_detect(const unsigned int* __restrict__ ei32) {
    __shared__ int nz;
    if (threadIdx.x == 0) nz = 0;
    __syncthreads();
    for (int i = threadIdx.x; i < 4096; i += blockDim.x)
        if (ei32[2 * i + 1] != 0u) atomicOr(&nz, 1);
    __syncthreads();
    if (threadIdx.x == 0) g_is64 = nz ? 0 : 1;
}

// ---------------- GEMM1: pre-split bf16, cp.async 4-stage, fp16 out ----------
__global__ void __launch_bounds__(256, 2) k_gemm1_mma(int M) {
    extern __shared__ __align__(16) uint8_t sm[];
    int tid = threadIdx.x, lane = tid & 31, wid = tid >> 5;
    int warp_m = wid & 1, warp_n = wid >> 1;
    int rowBase = blockIdx.y << 7, colBase = blockIdx.x << 7;
    uint32_t uS = smem_u32(sm);

    int cRow = tid >> 1, cHalf = tid & 1;
    uint32_t aSz = (rowBase + cRow) < M ? 16u : 0u;
    const __nv_bfloat16* Ah = g_xh + (size_t)(rowBase + cRow) * NFEAT + cHalf * 8;
    const __nv_bfloat16* Al = g_xl + (size_t)(rowBase + cRow) * NFEAT + cHalf * 8;
    const __nv_bfloat16* Bh = g_wth + (size_t)(colBase + cRow) * NFEAT + cHalf * 8;
    const __nv_bfloat16* Bl = g_wtl + (size_t)(colBase + cRow) * NFEAT + cHalf * 8;
    uint32_t cDst = (uint32_t)(cRow * ROWS_B + cHalf * 16);

    uint32_t aRel[4], bRel[2];
#pragma unroll
    for (int mt = 0; mt < 4; mt++)
        aRel[mt] = (uint32_t)((warp_m * 64 + mt * 16 + (lane & 15)) * ROWS_B
                              + (((lane >> 4) & 1) << 4));
    {
        int b_n = (lane & 7) | ((lane & 16) >> 1);
        int b_kb = (lane & 8) << 1;
#pragma unroll
        for (int bt = 0; bt < 2; bt++)
            bRel[bt] = (uint32_t)((warp_n * 32 + bt * 16 + b_n) * ROWS_B + b_kb);
    }

    float c[4][4][4];
#pragma unroll
    for (int i = 0; i < 4; i++)
#pragma unroll
        for (int j = 0; j < 4; j++)
#pragma unroll
            for (int q = 0; q < 4; q++) c[i][j][q] = 0.f;

    auto issue = [&](int kt, int buf) {
        uint32_t b = uS + (uint32_t)buf * STG_BYTES + cDst;
        CP16(b,          Ah + kt * 16, aSz);
        CP16(b + OFF_AL, Al + kt * 16, aSz);
        CP16(b + OFF_BH, Bh + kt * 16, 16u);
        CP16(b + OFF_BL, Bl + kt * 16, 16u);
    };

    issue(0, 0); CP_COMMIT();
    issue(1, 1); CP_COMMIT();
    issue(2, 2); CP_COMMIT();

    const int NT = NFEAT / 16;   // 32
    for (int kt = 0; kt < NT; kt++) {
        CP_WAIT2();
        __syncthreads();
        uint32_t base = uS + (uint32_t)(kt % NSTAGE) * STG_BYTES;

        uint32_t ah[4][4], bh[2][4];
#pragma unroll
        for (int mt = 0; mt < 4; mt++) ldsm4(base + aRel[mt], ah[mt]);
#pragma unroll
        for (int bt = 0; bt < 2; bt++) ldsm4(base + OFF_BH + bRel[bt], bh[bt]);
#pragma unroll
        for (int mt = 0; mt < 4; mt++)
#pragma unroll
            for (int nt = 0; nt < 4; nt++) {
                int bi = nt >> 1, bj = (nt & 1) << 1;
                MMA_BF16(c[mt][nt], ah[mt], bh[bi][bj], bh[bi][bj + 1]);
            }
        uint32_t bl[2][4];
#pragma unroll
        for (int bt = 0; bt < 2; bt++) ldsm4(base + OFF_BL + bRel[bt], bl[bt]);
#pragma unroll
        for (int mt = 0; mt < 4; mt++)
#pragma unroll
            for (int nt = 0; nt < 4; nt++) {
                int bi = nt >> 1, bj = (nt & 1) << 1;
                MMA_BF16(c[mt][nt], ah[mt], bl[bi][bj], bl[bi][bj + 1]);
            }
        uint32_t al[4][4];
#pragma unroll
        for (int mt = 0; mt < 4; mt++) ldsm4(base + OFF_AL + aRel[mt], al[mt]);
#pragma unroll
        for (int mt = 0; mt < 4; mt++)
#pragma unroll
            for (int nt = 0; nt < 4; nt++) {
                int bi = nt >> 1, bj = (nt & 1) << 1;
                MMA_BF16(c[mt][nt], al[mt], bh[bi][bj], bh[bi][bj + 1]);
            }

        if (kt + 3 < NT) issue(kt + 3, (kt + 3) % NSTAGE);
        CP_COMMIT();
    }

    // epilogue: fp16 output
#pragma unroll
    for (int mt = 0; mt < 4; mt++) {
        int r0 = rowBase + warp_m * 64 + mt * 16 + (lane >> 2);
#pragma unroll
        for (int nt = 0; nt < 4; nt++) {
            int col = colBase + warp_n * 32 + nt * 8 + ((lane & 3) << 1);
            if (r0 < M)
                *(__half2*)&g_h1h[(size_t)r0 * HHC + col] =
                    __floats2half2_rn(c[mt][nt][0], c[mt][nt][1]);
            if (r0 + 8 < M)
                *(__half2*)&g_h1h[(size_t)(r0 + 8) * HHC + col] =
                    __floats2half2_rn(c[mt][nt][2], c[mt][nt][3]);
        }
    }
}

// ---------------- CSR build ----------------
__global__ void k_init0(int M) {
    int i = blockIdx.x * blockDim.x + threadIdx.x;
    if (i < M) { g_deg[i] = 0; g_fill[i] = 0; }
}
__global__ void k_convcount(const void* __restrict__ ei, int E, int EN) {
    int e = blockIdx.x * blockDim.x + threadIdx.x;
    if (e >= EN) return;
    int s, d;
    if (e < E) {
        if (g_is64) {
            const long long* p = (const long long*)ei;
            s = (int)p[e]; d = (int)p[(size_t)E + e];
        } else {
            const int* p = (const int*)ei;
            s = p[e]; d = p[E + e];
        }
    } else { s = e - E; d = e - E; }
    g_src[e] = s; g_dst[e] = d;
    atomicAdd(&g_deg[d], 1);
}
__global__ void k_scan(int M) {
    __shared__ int ss[1024];
    int t = threadIdx.x;
    int CH = (M + 1023) >> 10;
    int base = t * CH;
    int sum = 0;
    for (int i = 0; i < CH; i++) { int idx = base + i; if (idx < M) sum += g_deg[idx]; }
    ss[t] = sum; __syncthreads();
    for (int off = 1; off < 1024; off <<= 1) {
        int v = (t >= off) ? ss[t - off] : 0;
        __syncthreads();
        ss[t] += v;
        __syncthreads();
    }
    int off = (t == 0) ? 0 : ss[t - 1];
    for (int i = 0; i < CH; i++) {
        int idx = base + i;
        if (idx < M) { g_row[idx] = off; off += g_deg[idx]; }
    }
    if (t == 1023) g_row[M] = ss[1023];
}
__global__ void k_scatter(int EN) {
    int e = blockIdx.x * blockDim.x + threadIdx.x;
    if (e >= EN) return;
    int d = g_dst[e];
    int p = g_row[d] + atomicAdd(&g_fill[d], 1);
    g_csrc[p] = g_src[e];
}

// ---------------- alpha1 (fp16 h1) ----------------
__global__ void k_alpha1(const float* __restrict__ asrc, const float* __restrict__ adst, int M) {
    int gw = (blockIdx.x * blockDim.x + threadIdx.x) >> 5;
    int lane = threadIdx.x & 31;
    if (gw >= M) return;
    const __half2* hr = (const __half2*)(g_h1h + (size_t)gw * HHC);
    const float2* as2p = (const float2*)asrc;
    const float2* ad2p = (const float2*)adst;
#pragma unroll
    for (int h = 0; h < NHEAD; h++) {
        float2 v = __half22float2(hr[h * 32 + lane]);
        float2 a = as2p[h * 32 + lane];
        float2 d = ad2p[h * 32 + lane];
        float sa = v.x * a.x + v.y * a.y;
        float sd = v.x * d.x + v.y * d.y;
#pragma unroll
        for (int o = 16; o; o >>= 1) {
            sa += __shfl_down_sync(0xffffffffu, sa, o);
            sd += __shfl_down_sync(0xffffffffu, sd, o);
        }
        if (lane == 0) { g_as1[gw * 8 + h] = sa; g_ad1[gw * 8 + h] = sd; }
    }
}

// ---------------- layer1 softmax: single pass, no max subtraction ------------
__global__ void k_soft1(int M) {
    int n = (blockIdx.x * blockDim.x + threadIdx.x) >> 5;
    int lane = threadIdx.x & 31;
    if (n >= M) return;
    int start = g_row[n], end = g_row[n + 1];
    int h = lane & 7, slot = lane >> 3;
    float ad = g_ad1[n * 8 + h];
    float den = 0.f;
    for (int p = start + slot; p < end; p += 4) {
        float v = g_as1[g_csrc[p] * 8 + h] + ad;
        v = v >= 0.f ? v : NEG * v;
        float ex = expf(v);
        g_ex1[(size_t)p * 8 + h] = ex;
        den += ex;
    }
    den += __shfl_xor_sync(0xffffffffu, den, 8);
    den += __shfl_xor_sync(0xffffffffu, den, 16);
    if (slot == 0) g_inv1[n * 8 + h] = 1.f / den;
}

// ---------------- layer1 aggregation (fp16 gather, unroll 2) -----------------
__global__ void __launch_bounds__(128) k_aggr1(float* __restrict__ emb,
                                               const float* __restrict__ b1) {
    int n = blockIdx.x;
    int t = threadIdx.x;
    __shared__ float sinv[8];
    if (t < 8) sinv[t] = g_inv1[n * 8 + t];
    __syncthreads();
    int start = g_row[n], end = g_row[n + 1];
    int h = t >> 4;
    float inv = sinv[h];
    float4 acc = make_float4(0.f, 0.f, 0.f, 0.f);
    int p = start;
    for (; p + 1 < end; p += 2) {
        int s0 = g_csrc[p], s1 = g_csrc[p + 1];
        float a0 = g_ex1[(size_t)p * 8 + h];
        float a1 = g_ex1[(size_t)(p + 1) * 8 + h];
        uint2 r0 = *(const uint2*)(g_h1h + (size_t)s0 * HHC + (t << 2));
        uint2 r1 = *(const uint2*)(g_h1h + (size_t)s1 * HHC + (t << 2));
        float2 f0a = __half22float2(*(__half2*)&r0.x);
        float2 f0b = __half22float2(*(__half2*)&r0.y);
        float2 f1a = __half22float2(*(__half2*)&r1.x);
        float2 f1b = __half22float2(*(__half2*)&r1.y);
        acc.x += a0 * f0a.x + a1 * f1a.x;
        acc.y += a0 * f0a.y + a1 * f1a.y;
        acc.z += a0 * f0b.x + a1 * f1b.x;
        acc.w += a0 * f0b.y + a1 * f1b.y;
    }
    if (p < end) {
        int s = g_csrc[p];
        float a = g_ex1[(size_t)p * 8 + h];
        uint2 raw = *(const uint2*)(g_h1h + (size_t)s * HHC + (t << 2));
        float2 f01 = __half22float2(*(__half2*)&raw.x);
        float2 f23 = __half22float2(*(__half2*)&raw.y);
        acc.x += a * f01.x; acc.y += a * f01.y;
        acc.z += a * f23.x; acc.w += a * f23.y;
    }
    acc.x *= inv; acc.y *= inv; acc.z *= inv; acc.w *= inv;
    float4 bv = ((const float4*)b1)[t];
    acc.x += bv.x; acc.y += bv.y; acc.z += bv.z; acc.w += bv.w;
    ((float4*)(emb + (size_t)n * HHC))[t] = acc;
    float ex = acc.x > 0.f ? acc.x : expm1f(acc.x);
    float ey = acc.y > 0.f ? acc.y : expm1f(acc.y);
    float ez = acc.z > 0.f ? acc.z : expm1f(acc.z);
    float ew = acc.w > 0.f ? acc.w : expm1f(acc.w);
    uint2 out;
    *(__half2*)&out.x = __floats2half2_rn(ex, ey);
    *(__half2*)&out.y = __floats2half2_rn(ez, ew);
    *(uint2*)(g_hactH + (size_t)n * HHC + (t << 2)) = out;
}

// ---------------- GEMM2 + alpha2 (fused, fp16 hact) ----------------
__global__ void k_gemm2(const float* __restrict__ W2, const float* __restrict__ asrc,
                        const float* __restrict__ adst, int M) {
    __shared__ float Ws[NFEAT * NCLS];
    for (int i = threadIdx.x; i < NFEAT * NCLS; i += 256) Ws[i] = W2[i];
    __syncthreads();
    int c = threadIdx.x & 15;
    int n = blockIdx.x * 16 + (threadIdx.x >> 4);
    if (n >= M) return;
    const uint4* hr8 = (const uint4*)(g_hactH + (size_t)n * HHC);
    float acc = 0.f;
#pragma unroll 4
    for (int k8 = 0; k8 < NFEAT / 8; k8++) {
        uint4 raw = hr8[k8];
        float2 f0 = __half22float2(*(__half2*)&raw.x);
        float2 f1 = __half22float2(*(__half2*)&raw.y);
        float2 f2 = __half22float2(*(__half2*)&raw.z);
        float2 f3 = __half22float2(*(__half2*)&raw.w);
        int k = k8 * 8;
        acc += f0.x * Ws[(k + 0) * NCLS + c] + f0.y * Ws[(k + 1) * NCLS + c];
        acc += f1.x * Ws[(k + 2) * NCLS + c] + f1.y * Ws[(k + 3) * NCLS + c];
        acc += f2.x * Ws[(k + 4) * NCLS + c] + f2.y * Ws[(k + 5) * NCLS + c];
        acc += f3.x * Ws[(k + 6) * NCLS + c] + f3.y * Ws[(k + 7) * NCLS + c];
    }
    g_h2[(size_t)n * NCLS + c] = acc;
    float sa = acc * asrc[c], sd = acc * adst[c];
#pragma unroll
    for (int o = 8; o; o >>= 1) {
        sa += __shfl_xor_sync(0xffffffffu, sa, o);
        sd += __shfl_xor_sync(0xffffffffu, sd, o);
    }
    if (c == 0) { g_as2[n] = sa; g_ad2[n] = sd; }
}

// ---------------- layer2 softmax: single pass ----------------
__global__ void k_soft2(int M) {
    int n = (blockIdx.x * blockDim.x + threadIdx.x) >> 5;
    int lane = threadIdx.x & 31;
    if (n >= M) return;
    int start = g_row[n], end = g_row[n + 1];
    float ad = g_ad2[n];
    float den = 0.f;
    for (int p = start + lane; p < end; p += 32) {
        float v = g_as2[g_csrc[p]] + ad;
        v = v >= 0.f ? v : NEG * v;
        float ex = expf(v);
        g_ex2[p] = ex;
        den += ex;
    }
#pragma unroll
    for (int o = 16; o; o >>= 1) den += __shfl_xor_sync(0xffffffffu, den, o);
    if (lane == 0) g_inv2[n] = 1.f / den;
}

// ---------------- layer2 aggregation ----------------
__global__ void k_aggr2(float* __restrict__ logits, const float* __restrict__ b2, int M) {
    int n = blockIdx.x * 8 + (threadIdx.x >> 4);
    int c = threadIdx.x & 15;
    if (n >= M) return;
    int start = g_row[n], end = g_row[n + 1];
    float inv = g_inv2[n];
    float acc = 0.f;
    int p = start;
    for (; p + 1 < end; p += 2) {
        float a0 = g_ex2[p], a1 = g_ex2[p + 1];
        float v0 = g_h2[(size_t)g_csrc[p] * NCLS + c];
        float v1 = g_h2[(size_t)g_csrc[p + 1] * NCLS + c];
        acc += a0 * v0 + a1 * v1;
    }
    if (p < end) acc += g_ex2[p] * g_h2[(size_t)g_csrc[p] * NCLS + c];
    logits[(size_t)n * NCLS + c] = acc * inv + b2[c];
}

// ---------------- launch ----------------
extern "C" void kernel_launch(void* const* d_in, const int* in_sizes, int n_in,
                              void* d_out, int out_size) {
    const float* x     = (const float*)d_in[0];
    const void*  ei    = d_in[1];
    const float* w1    = (const float*)d_in[2];
    const float* asrc1 = (const float*)d_in[3];
    const float* adst1 = (const float*)d_in[4];
    const float* b1    = (const float*)d_in[5];
    const float* w2    = (const float*)d_in[6];
    const float* asrc2 = (const float*)d_in[7];
    const float* adst2 = (const float*)d_in[8];
    const float* b2    = (const float*)d_in[9];

    const int M  = in_sizes[0] / NFEAT;     // 50000
    const int E  = in_sizes[1] / 2;         // 800000
    const int EN = E + M;                   // 850000

    float* logits = (float*)d_out;
    float* emb    = logits + (size_t)M * NCLS;

    static cudaStream_t s2 = nullptr;
    static cudaEvent_t evFork = nullptr, evJoin = nullptr;
    if (!s2) {
        cudaStreamCreateWithFlags(&s2, cudaStreamNonBlocking);
        cudaEventCreateWithFlags(&evFork, cudaEventDisableTiming);
        cudaEventCreateWithFlags(&evJoin, cudaEventDisableTiming);
    }

    cudaFuncSetAttribute(k_gemm1_mma, cudaFuncAttributeMaxDynamicSharedMemorySize, DSMEM_G1);

    // fork side stream for CSR build (independent of GEMM path)
    cudaEventRecord(evFork, 0);
    cudaStreamWaitEvent(s2, evFork, 0);

    size_t n4 = (size_t)M * NFEAT / 4;
    k_split_x<<<(unsigned)((n4 + 255) / 256), 256>>>(x, n4);          // k1 (main)
    {
        dim3 g(16, 16), b(32, 8);
        k_split_wt<<<g, b>>>(w1);                                      // k2 (main)
    }
    k_detect<<<1, 256, 0, s2>>>((const unsigned int*)ei);              // k3 (s2)
    {
        dim3 grid(HHC / 128, (M + 127) / 128);
        k_gemm1_mma<<<grid, 256, DSMEM_G1>>>(M);                       // k4 (main, profiled)
    }
    k_init0<<<(M + 255) / 256, 256, 0, s2>>>(M);
    k_convcount<<<(EN + 255) / 256, 256, 0, s2>>>(ei, E, EN);
    k_scan<<<1, 1024, 0, s2>>>(M);
    k_scatter<<<(EN + 255) / 256, 256, 0, s2>>>(EN);
    cudaEventRecord(evJoin, s2);

    k_alpha1<<<((M * 32) + 255) / 256, 256>>>(asrc1, adst1, M);

    // join: soft1 needs CSR + alpha1
    cudaStreamWaitEvent(0, evJoin, 0);
    k_soft1<<<((M * 32) + 255) / 256, 256>>>(M);
    k_aggr1<<<M, 128>>>(emb, b1);

    k_gemm2<<<(M + 15) / 16, 256>>>(w2, asrc2, adst2, M);
    k_soft2<<<((M * 32) + 255) / 256, 256>>>(M);
    k_aggr2<<<(M + 7) / 8, 128>>>(logits, b2, M);
}

// round 12
// speedup vs baseline: 4.3124x; 1.0122x over previous
#include <cuda_runtime.h>
#include <cuda_bf16.h>
#include <cuda_fp16.h>
#include <math.h>
#include <stdint.h>

#define NNODES 50000
#define NFEAT  512
#define HHC    512
#define NHEAD  8
#define NCLS   16
#define NEG    0.2f
#define MAXEN  850000

// GEMM1 smem staging: 4 regions (Ah, Al, Bh, Bl) x 128 rows x 48B pitch
#define ROWS_B    48
#define REGION    (128 * ROWS_B)     // 6144
#define OFF_AL    REGION
#define OFF_BH    (2 * REGION)
#define OFF_BL    (3 * REGION)
#define STG_BYTES (4 * REGION)       // 24576 per stage
#define NSTAGE    4
#define DSMEM_G1  (NSTAGE * STG_BYTES)  // 98304

// ---------------- scratch ----------------
__device__ __half g_h1h  [(size_t)NNODES * HHC];  // layer1 features, fp16
__device__ __half g_hactH[(size_t)NNODES * HHC];  // elu(emb), fp16
__device__ float g_h2  [(size_t)NNODES * NCLS];
__device__ __nv_bfloat16 g_xh[(size_t)NNODES * NFEAT];
__device__ __nv_bfloat16 g_xl[(size_t)NNODES * NFEAT];
__device__ __nv_bfloat16 g_wth[NFEAT * HHC];   // W1^T hi: [n][k]
__device__ __nv_bfloat16 g_wtl[NFEAT * HHC];   // W1^T lo
__device__ float g_as1[NNODES * NHEAD];
__device__ float g_ad1[NNODES * NHEAD];
__device__ float g_as2[NNODES];
__device__ float g_ad2[NNODES];
__device__ float g_ex1[(size_t)MAXEN * NHEAD];
__device__ float g_ex2[MAXEN];
__device__ int   g_src[MAXEN];
__device__ int   g_dst[MAXEN];
__device__ int   g_csrc[MAXEN];
__device__ int   g_row[NNODES + 1];
__device__ int   g_deg[NNODES];
__device__ int   g_fill[NNODES];
__device__ int   g_is64;

// ---------------- helpers ----------------
__device__ __forceinline__ uint32_t smem_u32(const void* p) {
    uint32_t a;
    asm("{ .reg .u64 t; cvta.to.shared.u64 t, %1; cvt.u32.u64 %0, t; }" : "=r"(a) : "l"(p));
    return a;
}
__device__ __forceinline__ void ldsm4(uint32_t addr, uint32_t* r) {
    asm volatile("ldmatrix.sync.aligned.m8n8.x4.shared.b16 {%0,%1,%2,%3}, [%4];"
                 : "=r"(r[0]), "=r"(r[1]), "=r"(r[2]), "=r"(r[3]) : "r"(addr));
}
#define MMA_BF16(c, a, b0, b1) \
    asm volatile("mma.sync.aligned.m16n8k16.row.col.f32.bf16.bf16.f32 " \
        "{%0,%1,%2,%3}, {%4,%5,%6,%7}, {%8,%9}, {%0,%1,%2,%3};" \
        : "+f"((c)[0]), "+f"((c)[1]), "+f"((c)[2]), "+f"((c)[3]) \
        : "r"((a)[0]), "r"((a)[1]), "r"((a)[2]), "r"((a)[3]), "r"(b0), "r"(b1))

#define CP16(dst, src, sz) \
    asm volatile("cp.async.cg.shared.global [%0], [%1], 16, %2;" \
                 :: "r"(dst), "l"(src), "r"(sz) : "memory")
#define CP_COMMIT() asm volatile("cp.async.commit_group;" ::: "memory")
#define CP_WAIT2()  asm volatile("cp.async.wait_group 2;" ::: "memory")

__device__ __forceinline__ void splitf(float a, __nv_bfloat16& h, __nv_bfloat16& l) {
    h = __float2bfloat16_rn(a);
    l = __float2bfloat16_rn(a - __bfloat162float(h));
}

// ---------------- split x -> bf16 hi/lo ----------------
__global__ void k_split_x(const float* __restrict__ x, size_t n4) {
    size_t i = (size_t)blockIdx.x * blockDim.x + threadIdx.x;
    if (i >= n4) return;
    float4 v = ((const float4*)x)[i];
    __nv_bfloat16 h0, h1, h2, h3, l0, l1, l2, l3;
    splitf(v.x, h0, l0); splitf(v.y, h1, l1);
    splitf(v.z, h2, l2); splitf(v.w, h3, l3);
    ushort4 H = make_ushort4(__bfloat16_as_ushort(h0), __bfloat16_as_ushort(h1),
                             __bfloat16_as_ushort(h2), __bfloat16_as_ushort(h3));
    ushort4 L = make_ushort4(__bfloat16_as_ushort(l0), __bfloat16_as_ushort(l1),
                             __bfloat16_as_ushort(l2), __bfloat16_as_ushort(l3));
    ((ushort4*)g_xh)[i] = H;
    ((ushort4*)g_xl)[i] = L;
}

// ---------------- W1 transpose + split ----------------
__global__ void k_split_wt(const float* __restrict__ w1) {
    __shared__ float t[32][33];
    int bx = blockIdx.x * 32, by = blockIdx.y * 32;
#pragma unroll
    for (int j = 0; j < 32; j += 8)
        t[threadIdx.y + j][threadIdx.x] = w1[(size_t)(by + threadIdx.y + j) * HHC + bx + threadIdx.x];
    __syncthreads();
#pragma unroll
    for (int j = 0; j < 32; j += 8) {
        float v = t[threadIdx.x][threadIdx.y + j];
        __nv_bfloat16 h, l;
        splitf(v, h, l);
        size_t o = (size_t)(bx + threadIdx.y + j) * NFEAT + by + threadIdx.x;
        g_wth[o] = h;
        g_wtl[o] = l;
    }
}

// ---------------- zero alpha accumulators ----------------
__global__ void k_zero_as(int M) {
    int i = blockIdx.x * blockDim.x + threadIdx.x;
    if (i < M * NHEAD) { g_as1[i] = 0.f; g_ad1[i] = 0.f; }
}

// ---------------- edge dtype sniff ----------------
__global__ void k_detect(const unsigned int* __restrict__ ei32) {
    __shared__ int nz;
    if (threadIdx.x == 0) nz = 0;
    __syncthreads();
    for (int i = threadIdx.x; i < 4096; i += blockDim.x)
        if (ei32[2 * i + 1] != 0u) atomicOr(&nz, 1);
    __syncthreads();
    if (threadIdx.x == 0) g_is64 = nz ? 0 : 1;
}

// ---------------- GEMM1 + fused alpha1 -----------------------
__global__ void __launch_bounds__(256, 2) k_gemm1_mma(
        const float* __restrict__ asrc1, const float* __restrict__ adst1, int M) {
    extern __shared__ __align__(16) uint8_t sm[];
    int tid = threadIdx.x, lane = tid & 31, wid = tid >> 5;
    int warp_m = wid & 1, warp_n = wid >> 1;
    int rowBase = blockIdx.y << 7, colBase = blockIdx.x << 7;
    uint32_t uS = smem_u32(sm);

    int cRow = tid >> 1, cHalf = tid & 1;
    uint32_t aSz = (rowBase + cRow) < M ? 16u : 0u;
    const __nv_bfloat16* Ah = g_xh + (size_t)(rowBase + cRow) * NFEAT + cHalf * 8;
    const __nv_bfloat16* Al = g_xl + (size_t)(rowBase + cRow) * NFEAT + cHalf * 8;
    const __nv_bfloat16* Bh = g_wth + (size_t)(colBase + cRow) * NFEAT + cHalf * 8;
    const __nv_bfloat16* Bl = g_wtl + (size_t)(colBase + cRow) * NFEAT + cHalf * 8;
    uint32_t cDst = (uint32_t)(cRow * ROWS_B + cHalf * 16);

    uint32_t aRel[4], bRel[2];
#pragma unroll
    for (int mt = 0; mt < 4; mt++)
        aRel[mt] = (uint32_t)((warp_m * 64 + mt * 16 + (lane & 15)) * ROWS_B
                              + (((lane >> 4) & 1) << 4));
    {
        int b_n = (lane & 7) | ((lane & 16) >> 1);
        int b_kb = (lane & 8) << 1;
#pragma unroll
        for (int bt = 0; bt < 2; bt++)
            bRel[bt] = (uint32_t)((warp_n * 32 + bt * 16 + b_n) * ROWS_B + b_kb);
    }

    float c[4][4][4];
#pragma unroll
    for (int i = 0; i < 4; i++)
#pragma unroll
        for (int j = 0; j < 4; j++)
#pragma unroll
            for (int q = 0; q < 4; q++) c[i][j][q] = 0.f;

    auto issue = [&](int kt, int buf) {
        uint32_t b = uS + (uint32_t)buf * STG_BYTES + cDst;
        CP16(b,          Ah + kt * 16, aSz);
        CP16(b + OFF_AL, Al + kt * 16, aSz);
        CP16(b + OFF_BH, Bh + kt * 16, 16u);
        CP16(b + OFF_BL, Bl + kt * 16, 16u);
    };

    issue(0, 0); CP_COMMIT();
    issue(1, 1); CP_COMMIT();
    issue(2, 2); CP_COMMIT();

    const int NT = NFEAT / 16;   // 32
    for (int kt = 0; kt < NT; kt++) {
        CP_WAIT2();
        __syncthreads();
        uint32_t base = uS + (uint32_t)(kt % NSTAGE) * STG_BYTES;

        uint32_t ah[4][4], bh[2][4];
#pragma unroll
        for (int mt = 0; mt < 4; mt++) ldsm4(base + aRel[mt], ah[mt]);
#pragma unroll
        for (int bt = 0; bt < 2; bt++) ldsm4(base + OFF_BH + bRel[bt], bh[bt]);
#pragma unroll
        for (int mt = 0; mt < 4; mt++)
#pragma unroll
            for (int nt = 0; nt < 4; nt++) {
                int bi = nt >> 1, bj = (nt & 1) << 1;
                MMA_BF16(c[mt][nt], ah[mt], bh[bi][bj], bh[bi][bj + 1]);
            }
        uint32_t bl[2][4];
#pragma unroll
        for (int bt = 0; bt < 2; bt++) ldsm4(base + OFF_BL + bRel[bt], bl[bt]);
#pragma unroll
        for (int mt = 0; mt < 4; mt++)
#pragma unroll
            for (int nt = 0; nt < 4; nt++) {
                int bi = nt >> 1, bj = (nt & 1) << 1;
                MMA_BF16(c[mt][nt], ah[mt], bl[bi][bj], bl[bi][bj + 1]);
            }
        uint32_t al[4][4];
#pragma unroll
        for (int mt = 0; mt < 4; mt++) ldsm4(base + OFF_AL + aRel[mt], al[mt]);
#pragma unroll
        for (int mt = 0; mt < 4; mt++)
#pragma unroll
            for (int nt = 0; nt < 4; nt++) {
                int bi = nt >> 1, bj = (nt & 1) << 1;
                MMA_BF16(c[mt][nt], al[mt], bh[bi][bj], bh[bi][bj + 1]);
            }

        if (kt + 3 < NT) issue(kt + 3, (kt + 3) % NSTAGE);
        CP_COMMIT();
    }

    // epilogue: fp16 output + fused alpha partials
    int head = (colBase + warp_n * 32) >> 6;
    float a_s[8], a_d[8];
#pragma unroll
    for (int j = 0; j < 8; j++) {
        int col = colBase + warp_n * 32 + (j >> 1) * 8 + ((lane & 3) << 1) + (j & 1);
        a_s[j] = asrc1[col];
        a_d[j] = adst1[col];
    }
#pragma unroll
    for (int mt = 0; mt < 4; mt++) {
        int r0 = rowBase + warp_m * 64 + mt * 16 + (lane >> 2);
        float sa0 = 0.f, sd0 = 0.f, sa8 = 0.f, sd8 = 0.f;
#pragma unroll
        for (int nt = 0; nt < 4; nt++) {
            int col = colBase + warp_n * 32 + nt * 8 + ((lane & 3) << 1);
            sa0 += c[mt][nt][0] * a_s[nt * 2] + c[mt][nt][1] * a_s[nt * 2 + 1];
            sd0 += c[mt][nt][0] * a_d[nt * 2] + c[mt][nt][1] * a_d[nt * 2 + 1];
            sa8 += c[mt][nt][2] * a_s[nt * 2] + c[mt][nt][3] * a_s[nt * 2 + 1];
            sd8 += c[mt][nt][2] * a_d[nt * 2] + c[mt][nt][3] * a_d[nt * 2 + 1];
            if (r0 < M)
                *(__half2*)&g_h1h[(size_t)r0 * HHC + col] =
                    __floats2half2_rn(c[mt][nt][0], c[mt][nt][1]);
            if (r0 + 8 < M)
                *(__half2*)&g_h1h[(size_t)(r0 + 8) * HHC + col] =
                    __floats2half2_rn(c[mt][nt][2], c[mt][nt][3]);
        }
        sa0 += __shfl_xor_sync(0xffffffffu, sa0, 1); sa0 += __shfl_xor_sync(0xffffffffu, sa0, 2);
        sd0 += __shfl_xor_sync(0xffffffffu, sd0, 1); sd0 += __shfl_xor_sync(0xffffffffu, sd0, 2);
        sa8 += __shfl_xor_sync(0xffffffffu, sa8, 1); sa8 += __shfl_xor_sync(0xffffffffu, sa8, 2);
        sd8 += __shfl_xor_sync(0xffffffffu, sd8, 1); sd8 += __shfl_xor_sync(0xffffffffu, sd8, 2);
        if ((lane & 3) == 0) {
            if (r0 < M) {
                atomicAdd(&g_as1[r0 * NHEAD + head], sa0);
                atomicAdd(&g_ad1[r0 * NHEAD + head], sd0);
            }
            if (r0 + 8 < M) {
                atomicAdd(&g_as1[(r0 + 8) * NHEAD + head], sa8);
                atomicAdd(&g_ad1[(r0 + 8) * NHEAD + head], sd8);
            }
        }
    }
}

// ---------------- CSR build ----------------
__global__ void k_init0(int M) {
    int i = blockIdx.x * blockDim.x + threadIdx.x;
    if (i < M) { g_deg[i] = 0; g_fill[i] = 0; }
}
__global__ void k_convcount(const void* __restrict__ ei, int E, int EN) {
    int e = blockIdx.x * blockDim.x + threadIdx.x;
    if (e >= EN) return;
    int s, d;
    if (e < E) {
        if (g_is64) {
            const long long* p = (const long long*)ei;
            s = (int)p[e]; d = (int)p[(size_t)E + e];
        } else {
            const int* p = (const int*)ei;
            s = p[e]; d = p[E + e];
        }
    } else { s = e - E; d = e - E; }
    g_src[e] = s; g_dst[e] = d;
    atomicAdd(&g_deg[d], 1);
}
__global__ void k_scan(int M) {
    __shared__ int ss[1024];
    int t = threadIdx.x;
    int CH = (M + 1023) >> 10;
    int base = t * CH;
    int sum = 0;
    for (int i = 0; i < CH; i++) { int idx = base + i; if (idx < M) sum += g_deg[idx]; }
    ss[t] = sum; __syncthreads();
    for (int off = 1; off < 1024; off <<= 1) {
        int v = (t >= off) ? ss[t - off] : 0;
        __syncthreads();
        ss[t] += v;
        __syncthreads();
    }
    int off = (t == 0) ? 0 : ss[t - 1];
    for (int i = 0; i < CH; i++) {
        int idx = base + i;
        if (idx < M) { g_row[idx] = off; off += g_deg[idx]; }
    }
    if (t == 1023) g_row[M] = ss[1023];
}
__global__ void k_scatter(int EN) {
    int e = blockIdx.x * blockDim.x + threadIdx.x;
    if (e >= EN) return;
    int d = g_dst[e];
    int p = g_row[d] + atomicAdd(&g_fill[d], 1);
    g_csrc[p] = g_src[e];
}

// ---------------- layer1: fused softmax + aggregation (block per node) -------
__global__ void __launch_bounds__(128) k_aggr1(float* __restrict__ emb,
                                               const float* __restrict__ b1) {
    int n = blockIdx.x;
    int t = threadIdx.x;
    __shared__ float sden[32];   // [warp][h]
    __shared__ float sinv[8];
    int start = g_row[n], end = g_row[n + 1];

    // pass1: softmax denominators; h = t&7, slot = t>>3 (0..15)
    {
        int h = t & 7, slot = t >> 3;
        float ad = g_ad1[n * NHEAD + h];
        float den = 0.f;
        for (int p = start + slot; p < end; p += 16) {
            float v = g_as1[g_csrc[p] * NHEAD + h] + ad;
            v = v >= 0.f ? v : NEG * v;
            float ex = __expf(v);
            g_ex1[(size_t)p * NHEAD + h] = ex;
            den += ex;
        }
        den += __shfl_xor_sync(0xffffffffu, den, 8);
        den += __shfl_xor_sync(0xffffffffu, den, 16);
        if ((t & 31) < 8) sden[(t >> 5) * 8 + h] = den;
    }
    __syncthreads();
    if (t < 8) sinv[t] = 1.f / (sden[t] + sden[8 + t] + sden[16 + t] + sden[24 + t]);
    __syncthreads();

    // pass2: aggregation; h = t>>4, 4 cols per thread
    int h = t >> 4;
    float inv = sinv[h];
    float4 acc = make_float4(0.f, 0.f, 0.f, 0.f);
    int p = start;
    for (; p + 1 < end; p += 2) {
        int s0 = g_csrc[p], s1 = g_csrc[p + 1];
        float a0 = g_ex1[(size_t)p * NHEAD + h];
        float a1 = g_ex1[(size_t)(p + 1) * NHEAD + h];
        uint2 r0 = *(const uint2*)(g_h1h + (size_t)s0 * HHC + (t << 2));
        uint2 r1 = *(const uint2*)(g_h1h + (size_t)s1 * HHC + (t << 2));
        float2 f0a = __half22float2(*(__half2*)&r0.x);
        float2 f0b = __half22float2(*(__half2*)&r0.y);
        float2 f1a = __half22float2(*(__half2*)&r1.x);
        float2 f1b = __half22float2(*(__half2*)&r1.y);
        acc.x += a0 * f0a.x + a1 * f1a.x;
        acc.y += a0 * f0a.y + a1 * f1a.y;
        acc.z += a0 * f0b.x + a1 * f1b.x;
        acc.w += a0 * f0b.y + a1 * f1b.y;
    }
    if (p < end) {
        int s = g_csrc[p];
        float a = g_ex1[(size_t)p * NHEAD + h];
        uint2 raw = *(const uint2*)(g_h1h + (size_t)s * HHC + (t << 2));
        float2 f01 = __half22float2(*(__half2*)&raw.x);
        float2 f23 = __half22float2(*(__half2*)&raw.y);
        acc.x += a * f01.x; acc.y += a * f01.y;
        acc.z += a * f23.x; acc.w += a * f23.y;
    }
    acc.x *= inv; acc.y *= inv; acc.z *= inv; acc.w *= inv;
    float4 bv = ((const float4*)b1)[t];
    acc.x += bv.x; acc.y += bv.y; acc.z += bv.z; acc.w += bv.w;
    ((float4*)(emb + (size_t)n * HHC))[t] = acc;
    float ex = acc.x > 0.f ? acc.x : expm1f(acc.x);
    float ey = acc.y > 0.f ? acc.y : expm1f(acc.y);
    float ez = acc.z > 0.f ? acc.z : expm1f(acc.z);
    float ew = acc.w > 0.f ? acc.w : expm1f(acc.w);
    uint2 out;
    *(__half2*)&out.x = __floats2half2_rn(ex, ey);
    *(__half2*)&out.y = __floats2half2_rn(ez, ew);
    *(uint2*)(g_hactH + (size_t)n * HHC + (t << 2)) = out;
}

// ---------------- GEMM2 + alpha2 (fused, fp16 hact) ----------------
__global__ void k_gemm2(const float* __restrict__ W2, const float* __restrict__ asrc,
                        const float* __restrict__ adst, int M) {
    __shared__ float Ws[NFEAT * NCLS];
    for (int i = threadIdx.x; i < NFEAT * NCLS; i += 256) Ws[i] = W2[i];
    __syncthreads();
    int c = threadIdx.x & 15;
    int n = blockIdx.x * 16 + (threadIdx.x >> 4);
    if (n >= M) return;
    const uint4* hr8 = (const uint4*)(g_hactH + (size_t)n * HHC);
    float acc = 0.f;
#pragma unroll 4
    for (int k8 = 0; k8 < NFEAT / 8; k8++) {
        uint4 raw = hr8[k8];
        float2 f0 = __half22float2(*(__half2*)&raw.x);
        float2 f1 = __half22float2(*(__half2*)&raw.y);
        float2 f2 = __half22float2(*(__half2*)&raw.z);
        float2 f3 = __half22float2(*(__half2*)&raw.w);
        int k = k8 * 8;
        acc += f0.x * Ws[(k + 0) * NCLS + c] + f0.y * Ws[(k + 1) * NCLS + c];
        acc += f1.x * Ws[(k + 2) * NCLS + c] + f1.y * Ws[(k + 3) * NCLS + c];
        acc += f2.x * Ws[(k + 4) * NCLS + c] + f2.y * Ws[(k + 5) * NCLS + c];
        acc += f3.x * Ws[(k + 6) * NCLS + c] + f3.y * Ws[(k + 7) * NCLS + c];
    }
    g_h2[(size_t)n * NCLS + c] = acc;
    float sa = acc * asrc[c], sd = acc * adst[c];
#pragma unroll
    for (int o = 8; o; o >>= 1) {
        sa += __shfl_xor_sync(0xffffffffu, sa, o);
        sd += __shfl_xor_sync(0xffffffffu, sd, o);
    }
    if (c == 0) { g_as2[n] = sa; g_ad2[n] = sd; }
}

// ---------------- layer2: fused softmax + aggregation (warp per node) --------
__global__ void k_l2(float* __restrict__ logits, const float* __restrict__ b2, int M) {
    int n = (blockIdx.x * blockDim.x + threadIdx.x) >> 5;
    int lane = threadIdx.x & 31;
    if (n >= M) return;
    int start = g_row[n], end = g_row[n + 1];
    float ad = g_ad2[n];
    float den = 0.f;
    for (int p = start + lane; p < end; p += 32) {
        float v = g_as2[g_csrc[p]] + ad;
        v = v >= 0.f ? v : NEG * v;
        float ex = __expf(v);
        g_ex2[p] = ex;
        den += ex;
    }
#pragma unroll
    for (int o = 16; o; o >>= 1) den += __shfl_xor_sync(0xffffffffu, den, o);
    float inv = 1.f / den;
    __threadfence_block();
    __syncwarp();
    int c = lane & 15, half = lane >> 4;
    float acc = 0.f;
    for (int p = start + half; p < end; p += 2)
        acc += g_ex2[p] * g_h2[(size_t)g_csrc[p] * NCLS + c];
    acc += __shfl_xor_sync(0xffffffffu, acc, 16);
    if (lane < 16) logits[(size_t)n * NCLS + lane] = acc * inv + b2[lane];
}

// ---------------- launch ----------------
extern "C" void kernel_launch(void* const* d_in, const int* in_sizes, int n_in,
                              void* d_out, int out_size) {
    const float* x     = (const float*)d_in[0];
    const void*  ei    = d_in[1];
    const float* w1    = (const float*)d_in[2];
    const float* asrc1 = (const float*)d_in[3];
    const float* adst1 = (const float*)d_in[4];
    const float* b1    = (const float*)d_in[5];
    const float* w2    = (const float*)d_in[6];
    const float* asrc2 = (const float*)d_in[7];
    const float* adst2 = (const float*)d_in[8];
    const float* b2    = (const float*)d_in[9];

    const int M  = in_sizes[0] / NFEAT;     // 50000
    const int E  = in_sizes[1] / 2;         // 800000
    const int EN = E + M;                   // 850000

    float* logits = (float*)d_out;
    float* emb    = logits + (size_t)M * NCLS;

    static cudaStream_t s2 = nullptr;
    static cudaEvent_t evFork = nullptr, evJoin = nullptr;
    if (!s2) {
        cudaStreamCreateWithFlags(&s2, cudaStreamNonBlocking);
        cudaEventCreateWithFlags(&evFork, cudaEventDisableTiming);
        cudaEventCreateWithFlags(&evJoin, cudaEventDisableTiming);
    }

    cudaFuncSetAttribute(k_gemm1_mma, cudaFuncAttributeMaxDynamicSharedMemorySize, DSMEM_G1);

    cudaEventRecord(evFork, 0);
    cudaStreamWaitEvent(s2, evFork, 0);

    size_t n4 = (size_t)M * NFEAT / 4;
    k_split_x<<<(unsigned)((n4 + 255) / 256), 256>>>(x, n4);          // 1 main
    {
        dim3 g(16, 16), b(32, 8);
        k_split_wt<<<g, b>>>(w1);                                      // 2 main
    }
    k_zero_as<<<(M * NHEAD + 255) / 256, 256>>>(M);                    // 3 main
    {
        dim3 grid(HHC / 128, (M + 127) / 128);
        k_gemm1_mma<<<grid, 256, DSMEM_G1>>>(asrc1, adst1, M);         // 4 main (profiled)
    }
    // side stream: CSR build, concurrent with gemm1
    k_detect<<<1, 256, 0, s2>>>((const unsigned int*)ei);
    k_init0<<<(M + 255) / 256, 256, 0, s2>>>(M);
    k_convcount<<<(EN + 255) / 256, 256, 0, s2>>>(ei, E, EN);
    k_scan<<<1, 1024, 0, s2>>>(M);
    k_scatter<<<(EN + 255) / 256, 256, 0, s2>>>(EN);
    cudaEventRecord(evJoin, s2);

    cudaStreamWaitEvent(0, evJoin, 0);
    k_aggr1<<<M, 128>>>(emb, b1);

    k_gemm2<<<(M + 15) / 16, 256>>>(w2, asrc2, adst2, M);
    k_l2<<<((M * 32) + 255) / 256, 256>>>(logits, b2, M);
}